// round 1
// baseline (speedup 1.0000x reference)
#include <cuda_runtime.h>
#include <cuda_bf16.h>
#include <math_constants.h>

#define NTOK   4096
#define DMODEL 768
#define NH     12
#define HD     64
#define KSEL   16
#define MDB    32768
#define NCH    8
#define CHUNK  (MDB/NCH)   /* 4096 keys per chunk */
#define DFF    3072

// ---------------- scratch (device globals; no allocation allowed) ----------
__device__ float g_ln  [NTOK*DMODEL];
__device__ float g_q   [NTOK*DMODEL];
__device__ float g_attn[NTOK*DMODEL];
__device__ float g_h   [NTOK*DMODEL];
__device__ float g_ff1 [NTOK*DFF];
__device__ float g_part_s[NTOK*NCH*KSEL];
__device__ int   g_part_i[NTOK*NCH*KSEL];
__device__ int   g_topk  [NTOK*KSEL];

// ---------------- helpers ---------------------------------------------------
__device__ __forceinline__ float blockReduceSum(float v, float* red) {
    #pragma unroll
    for (int o = 16; o > 0; o >>= 1) v += __shfl_xor_sync(0xffffffffu, v, o);
    int w = threadIdx.x >> 5, l = threadIdx.x & 31;
    if (l == 0) red[w] = v;
    __syncthreads();
    if (w == 0) {
        float t = (l < 8) ? red[l] : 0.f;
        #pragma unroll
        for (int o = 4; o > 0; o >>= 1) t += __shfl_xor_sync(0xffffffffu, t, o);
        if (l == 0) red[0] = t;
    }
    __syncthreads();
    float r = red[0];
    __syncthreads();
    return r;
}

__device__ __forceinline__ float gelu_tanh(float x) {
    return 0.5f * x * (1.f + tanhf(0.7978845608028654f * (x + 0.044715f * x * x * x)));
}

__device__ __forceinline__ bool better(float s1, int i1, float s2, int i2) {
    return (s1 > s2) || (s1 == s2 && i1 < i2);
}

// ---------------- layernorm (one block per row, 256 thr, 3 elems/thr) -------
__global__ __launch_bounds__(256) void ln_kernel(
    const float* __restrict__ x, const float* __restrict__ g,
    const float* __restrict__ b, float* __restrict__ y)
{
    __shared__ float red[8];
    int row = blockIdx.x;
    const float* xr = x + (size_t)row * DMODEL;
    int t = threadIdx.x;
    float v0 = xr[t], v1 = xr[t + 256], v2 = xr[t + 512];
    float mu = blockReduceSum(v0 + v1 + v2, red) * (1.f / DMODEL);
    float d0 = v0 - mu, d1 = v1 - mu, d2 = v2 - mu;
    float var = blockReduceSum(d0 * d0 + d1 * d1 + d2 * d2, red) * (1.f / DMODEL);
    float rs = rsqrtf(var + 1e-5f);
    float* yr = y + (size_t)row * DMODEL;
    yr[t]       = d0 * rs * g[t]       + b[t];
    yr[t + 256] = d1 * rs * g[t + 256] + b[t + 256];
    yr[t + 512] = d2 * rs * g[t + 512] + b[t + 512];
}

// ---------------- generic SGEMM: C[M,N] = A[M,K(lda)] @ B[K,N(ldb)] ----------
// 128x128 tile, BK=8, 256 threads, 8x8 micro-tile per thread.
enum { EPI_BIAS = 0, EPI_BIAS_RES = 1, EPI_GELU = 2 };

template <int EPI>
__global__ __launch_bounds__(256) void sgemm_kernel(
    const float* __restrict__ A, int lda,
    const float* __restrict__ B, int ldb,
    const float* __restrict__ bias,
    const float* __restrict__ res,
    float* __restrict__ C, int ldc, int Kd)
{
    __shared__ float As[8][128];
    __shared__ float Bs[8][128];
    int tid  = threadIdx.x;
    int brow = blockIdx.y * 128, bcol = blockIdx.x * 128;
    int arow = tid >> 1, acol = (tid & 1) * 4;
    int bkr  = tid >> 5, bcol4 = (tid & 31) * 4;
    const float* Ap = A + (size_t)(brow + arow) * lda + acol;
    const float* Bp = B + (size_t)bkr * ldb + bcol + bcol4;
    int rbase = (tid >> 4) * 4, cbase = (tid & 15) * 4;

    float acc[8][8];
    #pragma unroll
    for (int i = 0; i < 8; i++)
        #pragma unroll
        for (int j = 0; j < 8; j++) acc[i][j] = 0.f;

    for (int k0 = 0; k0 < Kd; k0 += 8) {
        float4 av = *reinterpret_cast<const float4*>(Ap + k0);
        float4 bv = *reinterpret_cast<const float4*>(Bp + (size_t)k0 * ldb);
        __syncthreads();
        As[acol + 0][arow] = av.x; As[acol + 1][arow] = av.y;
        As[acol + 2][arow] = av.z; As[acol + 3][arow] = av.w;
        *reinterpret_cast<float4*>(&Bs[bkr][bcol4]) = bv;
        __syncthreads();
        #pragma unroll
        for (int kk = 0; kk < 8; kk++) {
            float a[8], bb[8];
            *reinterpret_cast<float4*>(a)      = *reinterpret_cast<const float4*>(&As[kk][rbase]);
            *reinterpret_cast<float4*>(a + 4)  = *reinterpret_cast<const float4*>(&As[kk][rbase + 64]);
            *reinterpret_cast<float4*>(bb)     = *reinterpret_cast<const float4*>(&Bs[kk][cbase]);
            *reinterpret_cast<float4*>(bb + 4) = *reinterpret_cast<const float4*>(&Bs[kk][cbase + 64]);
            #pragma unroll
            for (int i = 0; i < 8; i++)
                #pragma unroll
                for (int j = 0; j < 8; j++) acc[i][j] += a[i] * bb[j];
        }
    }

    #pragma unroll
    for (int i = 0; i < 8; i++) {
        int r = brow + rbase + ((i < 4) ? i : 60 + i);  // i>=4 -> +64 offset group
        #pragma unroll
        for (int jg = 0; jg < 2; jg++) {
            int c = bcol + cbase + jg * 64;
            float4 bi = *reinterpret_cast<const float4*>(bias + c);
            float4 v;
            v.x = acc[i][jg * 4 + 0] + bi.x;
            v.y = acc[i][jg * 4 + 1] + bi.y;
            v.z = acc[i][jg * 4 + 2] + bi.z;
            v.w = acc[i][jg * 4 + 3] + bi.w;
            if (EPI == EPI_BIAS_RES) {
                float4 rv = *reinterpret_cast<const float4*>(res + (size_t)r * ldc + c);
                v.x += rv.x; v.y += rv.y; v.z += rv.z; v.w += rv.w;
            } else if (EPI == EPI_GELU) {
                v.x = gelu_tanh(v.x); v.y = gelu_tanh(v.y);
                v.z = gelu_tanh(v.z); v.w = gelu_tanh(v.w);
            }
            *reinterpret_cast<float4*>(C + (size_t)r * ldc + c) = v;
        }
    }
}

// ---------------- fused scores GEMM + per-row top-16 ------------------------
// grid(NCH, NTOK/128); block computes 128 queries x 4096 keys, streaming
// 128x128 score tiles through smem and keeping sorted top-16 per row.
__global__ __launch_bounds__(256) void score_topk_kernel(
    const float* __restrict__ q, const float* __restrict__ dbk,
    float* __restrict__ part_s, int* __restrict__ part_i)
{
    extern __shared__ float sm[];
    float (*As)[128] = (float(*)[128])sm;                         // 8x128
    float (*Bs)[128] = (float(*)[128])(sm + 8 * 128);             // 8x128
    float (*Sc)[132] = (float(*)[132])(sm + 2 * 8 * 128);         // 128x132
    float (*tks)[16] = (float(*)[16])(sm + 2 * 8 * 128 + 128 * 132);
    int   (*tki)[16] = (int  (*)[16])(sm + 2 * 8 * 128 + 128 * 132 + 128 * 16);

    int tid = threadIdx.x;
    int lane = tid & 31, wid = tid >> 5;
    int q0 = blockIdx.y * 128;
    int c0 = blockIdx.x * CHUNK;

    for (int i = tid; i < 128 * 16; i += 256) {
        ((float*)tks)[i] = -CUDART_INF_F;
        ((int*)tki)[i]   = 0x7fffffff;
    }
    __syncthreads();

    int arow = tid >> 1, acol = (tid & 1) * 4;
    int rbase = (tid >> 4) * 4, cbase = (tid & 15) * 4;
    const float* Aq = q + (size_t)(q0 + arow) * DMODEL + acol;

    for (int kt = 0; kt < CHUNK / 128; kt++) {
        int kb = c0 + kt * 128;
        const float* Bk = dbk + (size_t)(kb + arow) * DMODEL + acol;

        float acc[8][8];
        #pragma unroll
        for (int i = 0; i < 8; i++)
            #pragma unroll
            for (int j = 0; j < 8; j++) acc[i][j] = 0.f;

        for (int k0 = 0; k0 < DMODEL; k0 += 8) {
            float4 av = *reinterpret_cast<const float4*>(Aq + k0);
            float4 bv = *reinterpret_cast<const float4*>(Bk + k0);
            __syncthreads();
            As[acol + 0][arow] = av.x; As[acol + 1][arow] = av.y;
            As[acol + 2][arow] = av.z; As[acol + 3][arow] = av.w;
            Bs[acol + 0][arow] = bv.x; Bs[acol + 1][arow] = bv.y;
            Bs[acol + 2][arow] = bv.z; Bs[acol + 3][arow] = bv.w;
            __syncthreads();
            #pragma unroll
            for (int kk = 0; kk < 8; kk++) {
                float a[8], bb[8];
                *reinterpret_cast<float4*>(a)      = *reinterpret_cast<const float4*>(&As[kk][rbase]);
                *reinterpret_cast<float4*>(a + 4)  = *reinterpret_cast<const float4*>(&As[kk][rbase + 64]);
                *reinterpret_cast<float4*>(bb)     = *reinterpret_cast<const float4*>(&Bs[kk][cbase]);
                *reinterpret_cast<float4*>(bb + 4) = *reinterpret_cast<const float4*>(&Bs[kk][cbase + 64]);
                #pragma unroll
                for (int i = 0; i < 8; i++)
                    #pragma unroll
                    for (int j = 0; j < 8; j++) acc[i][j] += a[i] * bb[j];
            }
        }

        // dump score tile to smem (prev scan finished: loop-bottom sync)
        #pragma unroll
        for (int i = 0; i < 8; i++) {
            int r = rbase + ((i < 4) ? i : 60 + i);
            #pragma unroll
            for (int jg = 0; jg < 2; jg++) {
                int c = cbase + jg * 64;
                float4 v = make_float4(acc[i][jg * 4 + 0], acc[i][jg * 4 + 1],
                                       acc[i][jg * 4 + 2], acc[i][jg * 4 + 3]);
                *reinterpret_cast<float4*>(&Sc[r][c]) = v;
            }
        }
        __syncthreads();

        // top-16 update: warp `wid` owns rows [wid*16, wid*16+16)
        for (int rr = 0; rr < 16; rr++) {
            int r = wid * 16 + rr;
            #pragma unroll
            for (int j = 0; j < 4; j++) {
                int c = lane + j * 32;
                float s = Sc[r][c];
                int myid = kb + c;
                float thr = tks[r][15];
                bool cand = (s > thr) || (s == thr && myid < tki[r][15]);
                unsigned mmask = __ballot_sync(0xffffffffu, cand);
                while (mmask) {
                    int src = __ffs(mmask) - 1; mmask &= mmask - 1;
                    if (lane == src) {
                        float th2 = tks[r][15];
                        if (s > th2 || (s == th2 && myid < tki[r][15])) {
                            int p = 15;
                            while (p > 0 && (s > tks[r][p - 1] ||
                                             (s == tks[r][p - 1] && myid < tki[r][p - 1]))) {
                                tks[r][p] = tks[r][p - 1];
                                tki[r][p] = tki[r][p - 1];
                                p--;
                            }
                            tks[r][p] = s; tki[r][p] = myid;
                        }
                    }
                    __syncwarp();
                }
            }
        }
        __syncthreads();
    }

    for (int i = tid; i < 128 * 16; i += 256) {
        int r = i >> 4, j = i & 15;
        size_t o = (size_t)(q0 + r) * (NCH * KSEL) + blockIdx.x * KSEL + j;
        part_s[o] = tks[r][j];
        part_i[o] = tki[r][j];
    }
}

// ---------------- merge NCH partial top-16s -> final top-16 -----------------
__global__ __launch_bounds__(256) void merge_kernel(
    const float* __restrict__ ps, const int* __restrict__ pi, int* __restrict__ topk)
{
    int lane = threadIdx.x & 31;
    int row  = blockIdx.x * 8 + (threadIdx.x >> 5);
    float s[4]; int id[4];
    #pragma unroll
    for (int j = 0; j < 4; j++) {
        s[j]  = ps[(size_t)row * 128 + lane + 32 * j];
        id[j] = pi[(size_t)row * 128 + lane + 32 * j];
    }
    for (int t = 0; t < KSEL; t++) {
        float bs = s[0]; int bid = id[0];
        #pragma unroll
        for (int j = 1; j < 4; j++)
            if (better(s[j], id[j], bs, bid)) { bs = s[j]; bid = id[j]; }
        #pragma unroll
        for (int o = 16; o > 0; o >>= 1) {
            float os = __shfl_xor_sync(0xffffffffu, bs, o);
            int   oi = __shfl_xor_sync(0xffffffffu, bid, o);
            if (better(os, oi, bs, bid)) { bs = os; bid = oi; }
        }
        if (lane == 0) topk[row * KSEL + t] = bid;
        #pragma unroll
        for (int j = 0; j < 4; j++)
            if (id[j] == bid) { s[j] = -CUDART_INF_F; id[j] = 0x7fffffff; }
    }
}

// ---------------- per-token memory attention (gather + softmax) -------------
// block = token; warp = head (12 warps = 384 threads); 64 dims = 2 per lane.
__global__ __launch_bounds__(384) void attn_kernel(
    const float* __restrict__ q, const float* __restrict__ dbk,
    const float* __restrict__ dbv, const int* __restrict__ topk,
    float* __restrict__ out)
{
    __shared__ float sq[DMODEL];
    __shared__ int   sidx[KSEL];
    __shared__ float saw[NH][KSEL];
    int t = blockIdx.x;
    int tid = threadIdx.x, lane = tid & 31, w = tid >> 5;
    sq[tid]       = q[(size_t)t * DMODEL + tid];
    sq[tid + 384] = q[(size_t)t * DMODEL + tid + 384];
    if (tid < KSEL) sidx[tid] = topk[t * KSEL + tid];
    __syncthreads();

    float q1 = sq[w * HD + lane], q2 = sq[w * HD + lane + 32];
    for (int m = 0; m < KSEL; m++) {
        const float* kr = dbk + (size_t)sidx[m] * DMODEL + w * HD;
        float p = q1 * kr[lane] + q2 * kr[lane + 32];
        #pragma unroll
        for (int o = 16; o > 0; o >>= 1) p += __shfl_xor_sync(0xffffffffu, p, o);
        if (lane == 0) saw[w][m] = p * 0.125f;   // / sqrt(64)
    }
    __syncwarp();
    {
        float x = (lane < KSEL) ? saw[w][lane] : -CUDART_INF_F;
        float mx = x;
        #pragma unroll
        for (int o = 16; o > 0; o >>= 1) mx = fmaxf(mx, __shfl_xor_sync(0xffffffffu, mx, o));
        float e = (lane < KSEL) ? expf(x - mx) : 0.f;
        float se = e;
        #pragma unroll
        for (int o = 16; o > 0; o >>= 1) se += __shfl_xor_sync(0xffffffffu, se, o);
        if (lane < KSEL) saw[w][lane] = e / se;
    }
    __syncwarp();
    float a1 = 0.f, a2 = 0.f;
    for (int m = 0; m < KSEL; m++) {
        float aw = saw[w][m];
        const float* vr = dbv + (size_t)sidx[m] * DMODEL + w * HD;
        a1 += aw * vr[lane]; a2 += aw * vr[lane + 32];
    }
    out[(size_t)t * DMODEL + w * HD + lane]      = a1;
    out[(size_t)t * DMODEL + w * HD + lane + 32] = a2;
}

// ---------------- launch -----------------------------------------------------
extern "C" void kernel_launch(void* const* d_in, const int* in_sizes, int n_in,
                              void* d_out, int out_size)
{
    const float* prev   = (const float*)d_in[0];
    const float* dbk    = (const float*)d_in[1];
    const float* dbv    = (const float*)d_in[2];
    const float* ln1g   = (const float*)d_in[3];
    const float* ln1b   = (const float*)d_in[4];
    const float* cattnw = (const float*)d_in[5];
    const float* cattnb = (const float*)d_in[6];
    const float* cprojw = (const float*)d_in[7];
    const float* cprojb = (const float*)d_in[8];
    const float* ln2g   = (const float*)d_in[9];
    const float* ln2b   = (const float*)d_in[10];
    const float* fcw    = (const float*)d_in[11];
    const float* fcb    = (const float*)d_in[12];
    const float* projw  = (const float*)d_in[13];
    const float* projb  = (const float*)d_in[14];
    float* out = (float*)d_out;

    float *p_ln, *p_q, *p_attn, *p_h, *p_ff1, *p_parts;
    int *p_parti, *p_topk;
    cudaGetSymbolAddress((void**)&p_ln,    g_ln);
    cudaGetSymbolAddress((void**)&p_q,     g_q);
    cudaGetSymbolAddress((void**)&p_attn,  g_attn);
    cudaGetSymbolAddress((void**)&p_h,     g_h);
    cudaGetSymbolAddress((void**)&p_ff1,   g_ff1);
    cudaGetSymbolAddress((void**)&p_parts, g_part_s);
    cudaGetSymbolAddress((void**)&p_parti, g_part_i);
    cudaGetSymbolAddress((void**)&p_topk,  g_topk);

    // 1. LN1
    ln_kernel<<<NTOK, 256>>>(prev, ln1g, ln1b, p_ln);

    // 2. q = LN1(x) @ c_attn_w[:, :768] + c_attn_b[:768]  (k,v unused!)
    sgemm_kernel<EPI_BIAS><<<dim3(DMODEL / 128, NTOK / 128), 256>>>(
        p_ln, DMODEL, cattnw, 3 * DMODEL, cattnb, nullptr, p_q, DMODEL, DMODEL);

    // 3. scores = q @ db_keys^T fused with per-row top-16 (per chunk)
    int smem = (2 * 8 * 128 + 128 * 132 + 128 * 16 + 128 * 16) * 4;  // 92160 B
    cudaFuncSetAttribute(score_topk_kernel,
                         cudaFuncAttributeMaxDynamicSharedMemorySize, smem);
    score_topk_kernel<<<dim3(NCH, NTOK / 128), 256, smem>>>(p_q, dbk, p_parts, p_parti);

    // 4. merge chunk partials -> final top-16 indices
    merge_kernel<<<NTOK / 8, 256>>>(p_parts, p_parti, p_topk);

    // 5. per-token per-head softmax attention over 16 gathered memories
    attn_kernel<<<NTOK, 384>>>(p_q, dbk, dbv, p_topk, p_attn);

    // 6. h = attn @ c_proj_w + c_proj_b + residual
    sgemm_kernel<EPI_BIAS_RES><<<dim3(DMODEL / 128, NTOK / 128), 256>>>(
        p_attn, DMODEL, cprojw, DMODEL, cprojb, prev, p_h, DMODEL, DMODEL);

    // 7. LN2
    ln_kernel<<<NTOK, 256>>>(p_h, ln2g, ln2b, p_ln);

    // 8. ff1 = gelu(LN2(h) @ fc_w + fc_b)
    sgemm_kernel<EPI_GELU><<<dim3(DFF / 128, NTOK / 128), 256>>>(
        p_ln, DMODEL, fcw, DFF, fcb, nullptr, p_ff1, DFF, DMODEL);

    // 9. out = ff1 @ proj_w + proj_b + h
    sgemm_kernel<EPI_BIAS_RES><<<dim3(DMODEL / 128, NTOK / 128), 256>>>(
        p_ff1, DFF, projw, DMODEL, projb, p_h, out, DMODEL, DFF);
}

// round 3
// speedup vs baseline: 2.3581x; 2.3581x over previous
#include <cuda_runtime.h>
#include <cuda_bf16.h>
#include <math_constants.h>
#include <cstdint>

#define NTOK   4096
#define DMODEL 768
#define NH     12
#define HD     64
#define KSEL   16
#define MDB    32768
#define NCH    8
#define CHUNK  (MDB/NCH)   /* 4096 keys per chunk */
#define DFF    3072
#define NCAND  32          /* rescored candidates per token */

// ---------------- scratch (device globals; no allocation allowed) ----------
__device__ float g_ln  [NTOK*DMODEL];
__device__ float g_q   [NTOK*DMODEL];
__device__ float g_attn[NTOK*DMODEL];
__device__ float g_h   [NTOK*DMODEL];
__device__ float g_ff1 [NTOK*DFF];
__device__ __nv_bfloat16 g_qb[NTOK*DMODEL];
__device__ __nv_bfloat16 g_kb[MDB*DMODEL];
__device__ float g_part_s[NTOK*NCH*KSEL];
__device__ int   g_part_i[NTOK*NCH*KSEL];
__device__ int   g_cand  [NTOK*NCAND];
__device__ int   g_topk  [NTOK*KSEL];

// ---------------- helpers ---------------------------------------------------
__device__ __forceinline__ uint32_t smem_u32(const void* p) {
    uint32_t a;
    asm("{ .reg .u64 t; cvta.to.shared.u64 t, %1; cvt.u32.u64 %0, t; }" : "=r"(a) : "l"(p));
    return a;
}

__device__ __forceinline__ void ldsm_x4(uint32_t& r0, uint32_t& r1,
                                        uint32_t& r2, uint32_t& r3, uint32_t addr) {
    asm volatile("ldmatrix.sync.aligned.m8n8.x4.shared.b16 {%0,%1,%2,%3}, [%4];"
                 : "=r"(r0), "=r"(r1), "=r"(r2), "=r"(r3) : "r"(addr));
}

__device__ __forceinline__ void mma16816(float* c, const uint32_t* a, const uint32_t* b) {
    asm("mma.sync.aligned.m16n8k16.row.col.f32.bf16.bf16.f32 "
        "{%0,%1,%2,%3}, {%4,%5,%6,%7}, {%8,%9}, {%0,%1,%2,%3};"
        : "+f"(c[0]), "+f"(c[1]), "+f"(c[2]), "+f"(c[3])
        : "r"(a[0]), "r"(a[1]), "r"(a[2]), "r"(a[3]), "r"(b[0]), "r"(b[1]));
}

__device__ __forceinline__ float blockReduceSum(float v, float* red) {
    #pragma unroll
    for (int o = 16; o > 0; o >>= 1) v += __shfl_xor_sync(0xffffffffu, v, o);
    int w = threadIdx.x >> 5, l = threadIdx.x & 31;
    if (l == 0) red[w] = v;
    __syncthreads();
    if (w == 0) {
        float t = (l < 8) ? red[l] : 0.f;
        #pragma unroll
        for (int o = 4; o > 0; o >>= 1) t += __shfl_xor_sync(0xffffffffu, t, o);
        if (l == 0) red[0] = t;
    }
    __syncthreads();
    float r = red[0];
    __syncthreads();
    return r;
}

__device__ __forceinline__ float gelu_tanh(float x) {
    return 0.5f * x * (1.f + tanhf(0.7978845608028654f * (x + 0.044715f * x * x * x)));
}

__device__ __forceinline__ bool better(float s1, int i1, float s2, int i2) {
    return (s1 > s2) || (s1 == s2 && i1 < i2);
}

// ---------------- fp32 -> bf16 convert --------------------------------------
__global__ __launch_bounds__(256) void f2bf_kernel(
    const float* __restrict__ x, __nv_bfloat16* __restrict__ y)
{
    int i = (blockIdx.x * 256 + threadIdx.x) * 4;
    float4 v = *reinterpret_cast<const float4*>(x + i);
    __nv_bfloat162 a = __floats2bfloat162_rn(v.x, v.y);
    __nv_bfloat162 b = __floats2bfloat162_rn(v.z, v.w);
    reinterpret_cast<__nv_bfloat162*>(y + i)[0] = a;
    reinterpret_cast<__nv_bfloat162*>(y + i)[1] = b;
}

// ---------------- layernorm --------------------------------------------------
__global__ __launch_bounds__(256) void ln_kernel(
    const float* __restrict__ x, const float* __restrict__ g,
    const float* __restrict__ b, float* __restrict__ y)
{
    __shared__ float red[8];
    int row = blockIdx.x;
    const float* xr = x + (size_t)row * DMODEL;
    int t = threadIdx.x;
    float v0 = xr[t], v1 = xr[t + 256], v2 = xr[t + 512];
    float mu = blockReduceSum(v0 + v1 + v2, red) * (1.f / DMODEL);
    float d0 = v0 - mu, d1 = v1 - mu, d2 = v2 - mu;
    float var = blockReduceSum(d0 * d0 + d1 * d1 + d2 * d2, red) * (1.f / DMODEL);
    float rs = rsqrtf(var + 1e-5f);
    float* yr = y + (size_t)row * DMODEL;
    yr[t]       = d0 * rs * g[t]       + b[t];
    yr[t + 256] = d1 * rs * g[t + 256] + b[t + 256];
    yr[t + 512] = d2 * rs * g[t + 512] + b[t + 512];
}

// ---------------- generic SGEMM (unchanged, R1-proven) -----------------------
enum { EPI_BIAS = 0, EPI_BIAS_RES = 1, EPI_GELU = 2 };

template <int EPI>
__global__ __launch_bounds__(256) void sgemm_kernel(
    const float* __restrict__ A, int lda,
    const float* __restrict__ B, int ldb,
    const float* __restrict__ bias,
    const float* __restrict__ res,
    float* __restrict__ C, int ldc, int Kd)
{
    __shared__ float As[8][128];
    __shared__ float Bs[8][128];
    int tid  = threadIdx.x;
    int brow = blockIdx.y * 128, bcol = blockIdx.x * 128;
    int arow = tid >> 1, acol = (tid & 1) * 4;
    int bkr  = tid >> 5, bcol4 = (tid & 31) * 4;
    const float* Ap = A + (size_t)(brow + arow) * lda + acol;
    const float* Bp = B + (size_t)bkr * ldb + bcol + bcol4;
    int rbase = (tid >> 4) * 4, cbase = (tid & 15) * 4;

    float acc[8][8];
    #pragma unroll
    for (int i = 0; i < 8; i++)
        #pragma unroll
        for (int j = 0; j < 8; j++) acc[i][j] = 0.f;

    for (int k0 = 0; k0 < Kd; k0 += 8) {
        float4 av = *reinterpret_cast<const float4*>(Ap + k0);
        float4 bv = *reinterpret_cast<const float4*>(Bp + (size_t)k0 * ldb);
        __syncthreads();
        As[acol + 0][arow] = av.x; As[acol + 1][arow] = av.y;
        As[acol + 2][arow] = av.z; As[acol + 3][arow] = av.w;
        *reinterpret_cast<float4*>(&Bs[bkr][bcol4]) = bv;
        __syncthreads();
        #pragma unroll
        for (int kk = 0; kk < 8; kk++) {
            float a[8], bb[8];
            *reinterpret_cast<float4*>(a)      = *reinterpret_cast<const float4*>(&As[kk][rbase]);
            *reinterpret_cast<float4*>(a + 4)  = *reinterpret_cast<const float4*>(&As[kk][rbase + 64]);
            *reinterpret_cast<float4*>(bb)     = *reinterpret_cast<const float4*>(&Bs[kk][cbase]);
            *reinterpret_cast<float4*>(bb + 4) = *reinterpret_cast<const float4*>(&Bs[kk][cbase + 64]);
            #pragma unroll
            for (int i = 0; i < 8; i++)
                #pragma unroll
                for (int j = 0; j < 8; j++) acc[i][j] += a[i] * bb[j];
        }
    }

    #pragma unroll
    for (int i = 0; i < 8; i++) {
        int r = brow + rbase + ((i < 4) ? i : 60 + i);
        #pragma unroll
        for (int jg = 0; jg < 2; jg++) {
            int c = bcol + cbase + jg * 64;
            float4 bi = *reinterpret_cast<const float4*>(bias + c);
            float4 v;
            v.x = acc[i][jg * 4 + 0] + bi.x;
            v.y = acc[i][jg * 4 + 1] + bi.y;
            v.z = acc[i][jg * 4 + 2] + bi.z;
            v.w = acc[i][jg * 4 + 3] + bi.w;
            if (EPI == EPI_BIAS_RES) {
                float4 rv = *reinterpret_cast<const float4*>(res + (size_t)r * ldc + c);
                v.x += rv.x; v.y += rv.y; v.z += rv.z; v.w += rv.w;
            } else if (EPI == EPI_GELU) {
                v.x = gelu_tanh(v.x); v.y = gelu_tanh(v.y);
                v.z = gelu_tanh(v.z); v.w = gelu_tanh(v.w);
            }
            *reinterpret_cast<float4*>(C + (size_t)r * ldc + c) = v;
        }
    }
}

// ---------------- bf16 mma.sync score GEMM + per-row top-16 -----------------
// grid(NCH, 32); CTA = 128 queries x 4096-key chunk, K=768 in 12 slices of 64.
// smem layout (dynamic, 83968 B):
//   [0,8K)      tks lists   [8K,16K) tki lists   (persist whole kernel)
//   [16K,32K)   As bf16 128x64 (swizzled)        (mainloop)
//   [32K,48K)   Bs bf16 128x64 (swizzled)        (mainloop)
//   [16K,84K)   Sc f32 128x132                   (epilogue; overlaps As/Bs)
#define SC_LISTS 0
#define SC_A     16384
#define SC_B     32768
#define SC_SC    16384

__device__ __forceinline__ void stage64(char* dst, const __nv_bfloat16* __restrict__ src, int tid)
{
    #pragma unroll
    for (int it = 0; it < 4; it++) {
        int c = tid + it * 256;          // 1024 chunks = 128 rows x 8 x 16B
        int row = c >> 3, col = c & 7;
        uint4 v = *reinterpret_cast<const uint4*>(src + (size_t)row * DMODEL + col * 8);
        int scol = col ^ (row & 7);
        *reinterpret_cast<uint4*>(dst + row * 128 + scol * 16) = v;
    }
}

__global__ __launch_bounds__(256, 2) void score_topk_mma(
    const __nv_bfloat16* __restrict__ qb, const __nv_bfloat16* __restrict__ kb,
    float* __restrict__ part_s, int* __restrict__ part_i)
{
    extern __shared__ char dsm[];
    float (*tks)[16] = (float(*)[16])(dsm + SC_LISTS);
    int   (*tki)[16] = (int  (*)[16])(dsm + SC_LISTS + 8192);
    float (*Sc)[132] = (float(*)[132])(dsm + SC_SC);
    uint32_t sbase = smem_u32(dsm);
    const uint32_t SA = sbase + SC_A;
    const uint32_t SB = sbase + SC_B;

    int tid = threadIdx.x, lane = tid & 31, wid = tid >> 5;
    int warp_m = wid >> 2, warp_n = wid & 3;
    int q0 = blockIdx.y * 128;
    int c0 = blockIdx.x * CHUNK;

    for (int i = tid; i < 128 * 16; i += 256) {
        ((float*)tks)[i] = -CUDART_INF_F;
        ((int*)tki)[i]   = 0x7fffffff;
    }

    // precomputed ldmatrix lane row terms
    uint32_t a_rowoff[4], b_rowoff[2];
    int a_rx[4], b_rx[2];
    #pragma unroll
    for (int mt = 0; mt < 4; mt++) {
        int row = warp_m * 64 + mt * 16 + (lane & 15);
        a_rowoff[mt] = SA + row * 128;
        a_rx[mt] = row & 7;
    }
    #pragma unroll
    for (int pr = 0; pr < 2; pr++) {
        int row = warp_n * 32 + pr * 16 + (lane & 7) + ((lane >> 4) << 3);
        b_rowoff[pr] = SB + row * 128;
        b_rx[pr] = row & 7;
    }
    int a_ch = lane >> 4;        // A k-chunk half select
    int b_ch = (lane >> 3) & 1;  // B k-chunk half select

    for (int kt = 0; kt < CHUNK / 128; kt++) {
        int kb0 = c0 + kt * 128;

        float acc[4][4][4];
        #pragma unroll
        for (int mt = 0; mt < 4; mt++)
            #pragma unroll
            for (int nt = 0; nt < 4; nt++)
                #pragma unroll
                for (int r = 0; r < 4; r++) acc[mt][nt][r] = 0.f;

        for (int kc = 0; kc < DMODEL / 64; kc++) {
            __syncthreads();   // prior Sc/scan use (or prior stage) complete
            stage64(dsm + SC_A, qb + (size_t)q0  * DMODEL + kc * 64, tid);
            stage64(dsm + SC_B, kb + (size_t)kb0 * DMODEL + kc * 64, tid);
            __syncthreads();

            #pragma unroll
            for (int kk = 0; kk < 4; kk++) {
                uint32_t af[4][4], bf[2][4];
                #pragma unroll
                for (int mt = 0; mt < 4; mt++) {
                    int ch = kk * 2 + a_ch;
                    ldsm_x4(af[mt][0], af[mt][1], af[mt][2], af[mt][3],
                            a_rowoff[mt] + ((ch ^ a_rx[mt]) << 4));
                }
                #pragma unroll
                for (int pr = 0; pr < 2; pr++) {
                    int ch = kk * 2 + b_ch;
                    ldsm_x4(bf[pr][0], bf[pr][1], bf[pr][2], bf[pr][3],
                            b_rowoff[pr] + ((ch ^ b_rx[pr]) << 4));
                }
                #pragma unroll
                for (int mt = 0; mt < 4; mt++) {
                    mma16816(acc[mt][0], af[mt], &bf[0][0]);
                    mma16816(acc[mt][1], af[mt], &bf[0][2]);
                    mma16816(acc[mt][2], af[mt], &bf[1][0]);
                    mma16816(acc[mt][3], af[mt], &bf[1][2]);
                }
            }
        }

        // dump fragments to Sc (overlaps As/Bs; mainloop done)
        __syncthreads();
        #pragma unroll
        for (int mt = 0; mt < 4; mt++) {
            int r = warp_m * 64 + mt * 16 + (lane >> 2);
            #pragma unroll
            for (int nt = 0; nt < 4; nt++) {
                int c = warp_n * 32 + nt * 8 + 2 * (lane & 3);
                *reinterpret_cast<float2*>(&Sc[r][c])     = make_float2(acc[mt][nt][0], acc[mt][nt][1]);
                *reinterpret_cast<float2*>(&Sc[r + 8][c]) = make_float2(acc[mt][nt][2], acc[mt][nt][3]);
            }
        }
        __syncthreads();

        // R1-proven top-16 scan: warp wid owns rows [wid*16, wid*16+16)
        for (int rr = 0; rr < 16; rr++) {
            int r = wid * 16 + rr;
            #pragma unroll
            for (int j = 0; j < 4; j++) {
                int c = lane + j * 32;
                float s = Sc[r][c];
                int myid = kb0 + c;
                float thr = tks[r][15];
                bool cand = (s > thr) || (s == thr && myid < tki[r][15]);
                unsigned mmask = __ballot_sync(0xffffffffu, cand);
                while (mmask) {
                    int src = __ffs(mmask) - 1; mmask &= mmask - 1;
                    if (lane == src) {
                        float th2 = tks[r][15];
                        if (s > th2 || (s == th2 && myid < tki[r][15])) {
                            int p = 15;
                            while (p > 0 && (s > tks[r][p - 1] ||
                                             (s == tks[r][p - 1] && myid < tki[r][p - 1]))) {
                                tks[r][p] = tks[r][p - 1];
                                tki[r][p] = tki[r][p - 1];
                                p--;
                            }
                            tks[r][p] = s; tki[r][p] = myid;
                        }
                    }
                    __syncwarp();
                }
            }
        }
    }

    __syncthreads();
    for (int i = tid; i < 128 * 16; i += 256) {
        int r = i >> 4, j = i & 15;
        size_t o = (((size_t)(q0 + r)) * NCH + blockIdx.x) * KSEL + j;
        part_s[o] = tks[r][j];
        part_i[o] = tki[r][j];
    }
}

// ---------------- merge 128 bf16 candidates/row -> top-32 -------------------
__global__ __launch_bounds__(256) void merge32_kernel(
    const float* __restrict__ ps, const int* __restrict__ pi, int* __restrict__ cand)
{
    int lane = threadIdx.x & 31;
    int row  = blockIdx.x * 8 + (threadIdx.x >> 5);
    float s[4]; int id[4];
    #pragma unroll
    for (int j = 0; j < 4; j++) {
        size_t e = (size_t)row * 128 + lane + 32 * j;
        s[j]  = ps[e];
        id[j] = pi[e];
    }
    for (int t = 0; t < NCAND; t++) {
        float bs = s[0]; int bid = id[0];
        #pragma unroll
        for (int j = 1; j < 4; j++)
            if (better(s[j], id[j], bs, bid)) { bs = s[j]; bid = id[j]; }
        #pragma unroll
        for (int o = 16; o > 0; o >>= 1) {
            float os = __shfl_xor_sync(0xffffffffu, bs, o);
            int   oi = __shfl_xor_sync(0xffffffffu, bid, o);
            if (better(os, oi, bs, bid)) { bs = os; bid = oi; }
        }
        if (lane == 0) cand[row * NCAND + t] = bid;
        #pragma unroll
        for (int j = 0; j < 4; j++)
            if (id[j] == bid) { s[j] = -CUDART_INF_F; id[j] = 0x7fffffff; }
    }
}

// ---------------- exact fp32 rescore of 32 candidates -> final top-16 -------
__global__ __launch_bounds__(256) void rescore_kernel(
    const float* __restrict__ q, const float* __restrict__ dbk,
    const int* __restrict__ cand, int* __restrict__ topk)
{
    __shared__ float sq[DMODEL];
    __shared__ float ss[NCAND];
    __shared__ int   sid[NCAND];
    int t = blockIdx.x, tid = threadIdx.x;
    int w = tid >> 5, lane = tid & 31;
    sq[tid]       = q[(size_t)t * DMODEL + tid];
    sq[tid + 256] = q[(size_t)t * DMODEL + tid + 256];
    sq[tid + 512] = q[(size_t)t * DMODEL + tid + 512];
    if (tid < NCAND) sid[tid] = cand[t * NCAND + tid];
    __syncthreads();

    for (int cc = w; cc < NCAND; cc += 8) {
        const float* kr = dbk + (size_t)sid[cc] * DMODEL;
        float p = 0.f;
        #pragma unroll
        for (int j = 0; j < DMODEL / 32; j++)
            p += sq[lane + 32 * j] * kr[lane + 32 * j];
        #pragma unroll
        for (int o = 16; o > 0; o >>= 1) p += __shfl_xor_sync(0xffffffffu, p, o);
        if (lane == 0) ss[cc] = p;
    }
    __syncthreads();

    if (w == 0) {
        float s = ss[lane];
        int  id = sid[lane];
        for (int it = 0; it < KSEL; it++) {
            float bs = s; int bid = id;
            #pragma unroll
            for (int o = 16; o > 0; o >>= 1) {
                float os = __shfl_xor_sync(0xffffffffu, bs, o);
                int   oi = __shfl_xor_sync(0xffffffffu, bid, o);
                if (better(os, oi, bs, bid)) { bs = os; bid = oi; }
            }
            if (lane == 0) topk[t * KSEL + it] = bid;
            if (id == bid) { s = -CUDART_INF_F; id = 0x7fffffff; }
        }
    }
}

// ---------------- per-token memory attention (unchanged) --------------------
__global__ __launch_bounds__(384) void attn_kernel(
    const float* __restrict__ q, const float* __restrict__ dbk,
    const float* __restrict__ dbv, const int* __restrict__ topk,
    float* __restrict__ out)
{
    __shared__ float sq[DMODEL];
    __shared__ int   sidx[KSEL];
    __shared__ float saw[NH][KSEL];
    int t = blockIdx.x;
    int tid = threadIdx.x, lane = tid & 31, w = tid >> 5;
    sq[tid]       = q[(size_t)t * DMODEL + tid];
    sq[tid + 384] = q[(size_t)t * DMODEL + tid + 384];
    if (tid < KSEL) sidx[tid] = topk[t * KSEL + tid];
    __syncthreads();

    float q1 = sq[w * HD + lane], q2 = sq[w * HD + lane + 32];
    for (int m = 0; m < KSEL; m++) {
        const float* kr = dbk + (size_t)sidx[m] * DMODEL + w * HD;
        float p = q1 * kr[lane] + q2 * kr[lane + 32];
        #pragma unroll
        for (int o = 16; o > 0; o >>= 1) p += __shfl_xor_sync(0xffffffffu, p, o);
        if (lane == 0) saw[w][m] = p * 0.125f;
    }
    __syncwarp();
    {
        float x = (lane < KSEL) ? saw[w][lane] : -CUDART_INF_F;
        float mx = x;
        #pragma unroll
        for (int o = 16; o > 0; o >>= 1) mx = fmaxf(mx, __shfl_xor_sync(0xffffffffu, mx, o));
        float e = (lane < KSEL) ? expf(x - mx) : 0.f;
        float se = e;
        #pragma unroll
        for (int o = 16; o > 0; o >>= 1) se += __shfl_xor_sync(0xffffffffu, se, o);
        if (lane < KSEL) saw[w][lane] = e / se;
    }
    __syncwarp();
    float a1 = 0.f, a2 = 0.f;
    for (int m = 0; m < KSEL; m++) {
        float aw = saw[w][m];
        const float* vr = dbv + (size_t)sidx[m] * DMODEL + w * HD;
        a1 += aw * vr[lane]; a2 += aw * vr[lane + 32];
    }
    out[(size_t)t * DMODEL + w * HD + lane]      = a1;
    out[(size_t)t * DMODEL + w * HD + lane + 32] = a2;
}

// ---------------- launch -----------------------------------------------------
extern "C" void kernel_launch(void* const* d_in, const int* in_sizes, int n_in,
                              void* d_out, int out_size)
{
    const float* prev   = (const float*)d_in[0];
    const float* dbk    = (const float*)d_in[1];
    const float* dbv    = (const float*)d_in[2];
    const float* ln1g   = (const float*)d_in[3];
    const float* ln1b   = (const float*)d_in[4];
    const float* cattnw = (const float*)d_in[5];
    const float* cattnb = (const float*)d_in[6];
    const float* cprojw = (const float*)d_in[7];
    const float* cprojb = (const float*)d_in[8];
    const float* ln2g   = (const float*)d_in[9];
    const float* ln2b   = (const float*)d_in[10];
    const float* fcw    = (const float*)d_in[11];
    const float* fcb    = (const float*)d_in[12];
    const float* projw  = (const float*)d_in[13];
    const float* projb  = (const float*)d_in[14];
    float* out = (float*)d_out;

    float *p_ln, *p_q, *p_attn, *p_h, *p_ff1, *p_parts;
    __nv_bfloat16 *p_qb, *p_kb;
    int *p_parti, *p_cand, *p_topk;
    cudaGetSymbolAddress((void**)&p_ln,    g_ln);
    cudaGetSymbolAddress((void**)&p_q,     g_q);
    cudaGetSymbolAddress((void**)&p_attn,  g_attn);
    cudaGetSymbolAddress((void**)&p_h,     g_h);
    cudaGetSymbolAddress((void**)&p_ff1,   g_ff1);
    cudaGetSymbolAddress((void**)&p_qb,    g_qb);
    cudaGetSymbolAddress((void**)&p_kb,    g_kb);
    cudaGetSymbolAddress((void**)&p_parts, g_part_s);
    cudaGetSymbolAddress((void**)&p_parti, g_part_i);
    cudaGetSymbolAddress((void**)&p_cand,  g_cand);
    cudaGetSymbolAddress((void**)&p_topk,  g_topk);

    // 1. LN1
    ln_kernel<<<NTOK, 256>>>(prev, ln1g, ln1b, p_ln);

    // 2. q = LN1(x) @ c_attn_w[:, :768] + c_attn_b[:768]  (k,v unused)
    sgemm_kernel<EPI_BIAS><<<dim3(DMODEL / 128, NTOK / 128), 256>>>(
        p_ln, DMODEL, cattnw, 3 * DMODEL, cattnb, nullptr, p_q, DMODEL, DMODEL);

    // 3. bf16 conversions for tensor-core scoring
    f2bf_kernel<<<(NTOK * DMODEL) / 1024, 256>>>(p_q, p_qb);
    f2bf_kernel<<<(MDB * DMODEL) / 1024, 256>>>(dbk, p_kb);

    // 4. bf16 mma.sync score GEMM + per-chunk top-16 lists
    int smem = 16384 + 128 * 132 * 4;  // 83968 B
    cudaFuncSetAttribute(score_topk_mma,
                         cudaFuncAttributeMaxDynamicSharedMemorySize, smem);
    score_topk_mma<<<dim3(NCH, NTOK / 128), 256, smem>>>(p_qb, p_kb, p_parts, p_parti);

    // 5. merge 128 bf16 candidates -> top-32 per token
    merge32_kernel<<<NTOK / 8, 256>>>(p_parts, p_parti, p_cand);

    // 6. exact fp32 rescore of top-32 -> final top-16 (jax tie-break)
    rescore_kernel<<<NTOK, 256>>>(p_q, dbk, p_cand, p_topk);

    // 7. per-token per-head softmax attention over 16 gathered memories
    attn_kernel<<<NTOK, 384>>>(p_q, dbk, dbv, p_topk, p_attn);

    // 8. h = attn @ c_proj_w + c_proj_b + residual
    sgemm_kernel<EPI_BIAS_RES><<<dim3(DMODEL / 128, NTOK / 128), 256>>>(
        p_attn, DMODEL, cprojw, DMODEL, cprojb, prev, p_h, DMODEL, DMODEL);

    // 9. LN2
    ln_kernel<<<NTOK, 256>>>(p_h, ln2g, ln2b, p_ln);

    // 10. ff1 = gelu(LN2(h) @ fc_w + fc_b)
    sgemm_kernel<EPI_GELU><<<dim3(DFF / 128, NTOK / 128), 256>>>(
        p_ln, DMODEL, fcw, DFF, fcb, nullptr, p_ff1, DFF, DMODEL);

    // 11. out = ff1 @ proj_w + proj_b + h
    sgemm_kernel<EPI_BIAS_RES><<<dim3(DMODEL / 128, NTOK / 128), 256>>>(
        p_ff1, DFF, projw, DMODEL, projb, p_h, out, DMODEL, DFF);
}

// round 4
// speedup vs baseline: 3.0483x; 1.2927x over previous
#include <cuda_runtime.h>
#include <cuda_bf16.h>
#include <math_constants.h>
#include <cstdint>

#define NTOK   4096
#define DMODEL 768
#define NH     12
#define HD     64
#define KSEL   16
#define MDB    32768
#define NCH    8
#define CHUNK  (MDB/NCH)   /* 4096 keys per chunk */
#define DFF    3072
#define NCAND  32          /* rescored candidates per token */

// ---------------- scratch (device globals; no allocation allowed) ----------
__device__ float g_ln  [NTOK*DMODEL];
__device__ float g_q   [NTOK*DMODEL];
__device__ float g_attn[NTOK*DMODEL];
__device__ float g_h   [NTOK*DMODEL];
__device__ float g_ff1 [NTOK*DFF];
__device__ __nv_bfloat16 g_qb[NTOK*DMODEL];
__device__ __nv_bfloat16 g_kb[MDB*DMODEL];
__device__ float g_part_s[NTOK*NCH*KSEL];
__device__ int   g_part_i[NTOK*NCH*KSEL];
__device__ int   g_cand  [NTOK*NCAND];
__device__ int   g_topk  [NTOK*KSEL];

// ---------------- helpers ---------------------------------------------------
__device__ __forceinline__ uint32_t smem_u32(const void* p) {
    uint32_t a;
    asm("{ .reg .u64 t; cvta.to.shared.u64 t, %1; cvt.u32.u64 %0, t; }" : "=r"(a) : "l"(p));
    return a;
}

__device__ __forceinline__ void ldsm_x4(uint32_t& r0, uint32_t& r1,
                                        uint32_t& r2, uint32_t& r3, uint32_t addr) {
    asm volatile("ldmatrix.sync.aligned.m8n8.x4.shared.b16 {%0,%1,%2,%3}, [%4];"
                 : "=r"(r0), "=r"(r1), "=r"(r2), "=r"(r3) : "r"(addr));
}

__device__ __forceinline__ void mma16816(float* c, const uint32_t* a, const uint32_t* b) {
    asm("mma.sync.aligned.m16n8k16.row.col.f32.bf16.bf16.f32 "
        "{%0,%1,%2,%3}, {%4,%5,%6,%7}, {%8,%9}, {%0,%1,%2,%3};"
        : "+f"(c[0]), "+f"(c[1]), "+f"(c[2]), "+f"(c[3])
        : "r"(a[0]), "r"(a[1]), "r"(a[2]), "r"(a[3]), "r"(b[0]), "r"(b[1]));
}

__device__ __forceinline__ uint32_t f2tf32(float f) {
    uint32_t o; asm("cvt.rna.tf32.f32 %0, %1;" : "=r"(o) : "f"(f)); return o;
}

__device__ __forceinline__ void mma_tf32(float* c, const uint32_t* a, const uint32_t* b) {
    asm("mma.sync.aligned.m16n8k8.row.col.f32.tf32.tf32.f32 "
        "{%0,%1,%2,%3}, {%4,%5,%6,%7}, {%8,%9}, {%0,%1,%2,%3};"
        : "+f"(c[0]), "+f"(c[1]), "+f"(c[2]), "+f"(c[3])
        : "r"(a[0]), "r"(a[1]), "r"(a[2]), "r"(a[3]), "r"(b[0]), "r"(b[1]));
}

#define CP_ASYNC16(dst, src) \
    asm volatile("cp.async.cg.shared.global [%0], [%1], 16;" :: "r"(dst), "l"(src))
#define CP_COMMIT()  asm volatile("cp.async.commit_group;" ::: "memory")
#define CP_WAIT0()   asm volatile("cp.async.wait_group 0;" ::: "memory")

__device__ __forceinline__ float blockReduceSum(float v, float* red) {
    #pragma unroll
    for (int o = 16; o > 0; o >>= 1) v += __shfl_xor_sync(0xffffffffu, v, o);
    int w = threadIdx.x >> 5, l = threadIdx.x & 31;
    if (l == 0) red[w] = v;
    __syncthreads();
    if (w == 0) {
        float t = (l < 8) ? red[l] : 0.f;
        #pragma unroll
        for (int o = 4; o > 0; o >>= 1) t += __shfl_xor_sync(0xffffffffu, t, o);
        if (l == 0) red[0] = t;
    }
    __syncthreads();
    float r = red[0];
    __syncthreads();
    return r;
}

__device__ __forceinline__ float gelu_tanh(float x) {
    return 0.5f * x * (1.f + tanhf(0.7978845608028654f * (x + 0.044715f * x * x * x)));
}

__device__ __forceinline__ bool better(float s1, int i1, float s2, int i2) {
    return (s1 > s2) || (s1 == s2 && i1 < i2);
}

// ---------------- fp32 -> bf16 convert --------------------------------------
__global__ __launch_bounds__(256) void f2bf_kernel(
    const float* __restrict__ x, __nv_bfloat16* __restrict__ y)
{
    int i = (blockIdx.x * 256 + threadIdx.x) * 4;
    float4 v = *reinterpret_cast<const float4*>(x + i);
    __nv_bfloat162 a = __floats2bfloat162_rn(v.x, v.y);
    __nv_bfloat162 b = __floats2bfloat162_rn(v.z, v.w);
    reinterpret_cast<__nv_bfloat162*>(y + i)[0] = a;
    reinterpret_cast<__nv_bfloat162*>(y + i)[1] = b;
}

// ---------------- layernorm --------------------------------------------------
__global__ __launch_bounds__(256) void ln_kernel(
    const float* __restrict__ x, const float* __restrict__ g,
    const float* __restrict__ b, float* __restrict__ y)
{
    __shared__ float red[8];
    int row = blockIdx.x;
    const float* xr = x + (size_t)row * DMODEL;
    int t = threadIdx.x;
    float v0 = xr[t], v1 = xr[t + 256], v2 = xr[t + 512];
    float mu = blockReduceSum(v0 + v1 + v2, red) * (1.f / DMODEL);
    float d0 = v0 - mu, d1 = v1 - mu, d2 = v2 - mu;
    float var = blockReduceSum(d0 * d0 + d1 * d1 + d2 * d2, red) * (1.f / DMODEL);
    float rs = rsqrtf(var + 1e-5f);
    float* yr = y + (size_t)row * DMODEL;
    yr[t]       = d0 * rs * g[t]       + b[t];
    yr[t + 256] = d1 * rs * g[t + 256] + b[t + 256];
    yr[t + 512] = d2 * rs * g[t + 512] + b[t + 512];
}

// ---------------- fp32 SGEMM (only used for q; preserves selection) ---------
enum { EPI_BIAS = 0, EPI_BIAS_RES = 1, EPI_GELU = 2 };

template <int EPI>
__global__ __launch_bounds__(256) void sgemm_kernel(
    const float* __restrict__ A, int lda,
    const float* __restrict__ B, int ldb,
    const float* __restrict__ bias,
    const float* __restrict__ res,
    float* __restrict__ C, int ldc, int Kd)
{
    __shared__ float As[8][128];
    __shared__ float Bs[8][128];
    int tid  = threadIdx.x;
    int brow = blockIdx.y * 128, bcol = blockIdx.x * 128;
    int arow = tid >> 1, acol = (tid & 1) * 4;
    int bkr  = tid >> 5, bcol4 = (tid & 31) * 4;
    const float* Ap = A + (size_t)(brow + arow) * lda + acol;
    const float* Bp = B + (size_t)bkr * ldb + bcol + bcol4;
    int rbase = (tid >> 4) * 4, cbase = (tid & 15) * 4;

    float acc[8][8];
    #pragma unroll
    for (int i = 0; i < 8; i++)
        #pragma unroll
        for (int j = 0; j < 8; j++) acc[i][j] = 0.f;

    for (int k0 = 0; k0 < Kd; k0 += 8) {
        float4 av = *reinterpret_cast<const float4*>(Ap + k0);
        float4 bv = *reinterpret_cast<const float4*>(Bp + (size_t)k0 * ldb);
        __syncthreads();
        As[acol + 0][arow] = av.x; As[acol + 1][arow] = av.y;
        As[acol + 2][arow] = av.z; As[acol + 3][arow] = av.w;
        *reinterpret_cast<float4*>(&Bs[bkr][bcol4]) = bv;
        __syncthreads();
        #pragma unroll
        for (int kk = 0; kk < 8; kk++) {
            float a[8], bb[8];
            *reinterpret_cast<float4*>(a)      = *reinterpret_cast<const float4*>(&As[kk][rbase]);
            *reinterpret_cast<float4*>(a + 4)  = *reinterpret_cast<const float4*>(&As[kk][rbase + 64]);
            *reinterpret_cast<float4*>(bb)     = *reinterpret_cast<const float4*>(&Bs[kk][cbase]);
            *reinterpret_cast<float4*>(bb + 4) = *reinterpret_cast<const float4*>(&Bs[kk][cbase + 64]);
            #pragma unroll
            for (int i = 0; i < 8; i++)
                #pragma unroll
                for (int j = 0; j < 8; j++) acc[i][j] += a[i] * bb[j];
        }
    }

    #pragma unroll
    for (int i = 0; i < 8; i++) {
        int r = brow + rbase + ((i < 4) ? i : 60 + i);
        #pragma unroll
        for (int jg = 0; jg < 2; jg++) {
            int c = bcol + cbase + jg * 64;
            float4 bi = *reinterpret_cast<const float4*>(bias + c);
            float4 v;
            v.x = acc[i][jg * 4 + 0] + bi.x;
            v.y = acc[i][jg * 4 + 1] + bi.y;
            v.z = acc[i][jg * 4 + 2] + bi.z;
            v.w = acc[i][jg * 4 + 3] + bi.w;
            if (EPI == EPI_BIAS_RES) {
                float4 rv = *reinterpret_cast<const float4*>(res + (size_t)r * ldc + c);
                v.x += rv.x; v.y += rv.y; v.z += rv.z; v.w += rv.w;
            } else if (EPI == EPI_GELU) {
                v.x = gelu_tanh(v.x); v.y = gelu_tanh(v.y);
                v.z = gelu_tanh(v.z); v.w = gelu_tanh(v.w);
            }
            *reinterpret_cast<float4*>(C + (size_t)r * ldc + c) = v;
        }
    }
}

// ---------------- tf32 tensor-core GEMM for value path (c_proj/fc/proj) -----
// C[M,N] = A[M,K] @ B[K,N], 128x128x16 tiles, 8 warps (2x4), 64x32 per warp.
// Packed smem: pairs (k, k+4) adjacent -> LDS.64 fragment loads.
#define TFP 18

template <int EPI>
__global__ __launch_bounds__(256, 2) void tgemm_kernel(
    const float* __restrict__ A, int lda,
    const float* __restrict__ B, int ldb,
    const float* __restrict__ bias,
    const float* __restrict__ res,
    float* __restrict__ C, int ldc, int Kd)
{
    __shared__ uint32_t As[128 * TFP];
    __shared__ uint32_t Bs[128 * TFP];
    int tid = threadIdx.x, lane = tid & 31, wid = tid >> 5;
    int warp_m = wid >> 2, warp_n = wid & 3;
    int brow = blockIdx.y * 128, bcol = blockIdx.x * 128;

    float acc[4][4][4];
    #pragma unroll
    for (int mt = 0; mt < 4; mt++)
        #pragma unroll
        for (int nt = 0; nt < 4; nt++)
            #pragma unroll
            for (int r = 0; r < 4; r++) acc[mt][nt][r] = 0.f;

    int ar = tid >> 1, ah = tid & 1;   // A stager: row, k-half
    int bn = tid >> 1, bh = tid & 1;   // B stager: n col, k-half
    const float* Ap = A + (size_t)(brow + ar) * lda + ah * 8;
    const float* Bp = B + (size_t)(bh * 8) * ldb + bcol + bn;
    uint32_t* Asw = As + ar * TFP + ah * 8;
    uint32_t* Bsw = Bs + bn * TFP + bh * 8;

    for (int kb = 0; kb < Kd; kb += 16) {
        float4 ax = *reinterpret_cast<const float4*>(Ap + kb);
        float4 ay = *reinterpret_cast<const float4*>(Ap + kb + 4);
        float bv[8];
        #pragma unroll
        for (int j = 0; j < 8; j++) bv[j] = Bp[(size_t)(kb + j) * ldb];
        __syncthreads();
        Asw[0] = f2tf32(ax.x); Asw[1] = f2tf32(ay.x);
        Asw[2] = f2tf32(ax.y); Asw[3] = f2tf32(ay.y);
        Asw[4] = f2tf32(ax.z); Asw[5] = f2tf32(ay.z);
        Asw[6] = f2tf32(ax.w); Asw[7] = f2tf32(ay.w);
        #pragma unroll
        for (int m = 0; m < 4; m++) {
            Bsw[2 * m]     = f2tf32(bv[m]);
            Bsw[2 * m + 1] = f2tf32(bv[m + 4]);
        }
        __syncthreads();
        #pragma unroll
        for (int j = 0; j < 2; j++) {
            uint32_t a[4][4], b[4][2];
            #pragma unroll
            for (int mt = 0; mt < 4; mt++) {
                int row = warp_m * 64 + mt * 16 + (lane >> 2);
                const uint32_t* p = As + row * TFP + j * 8 + 2 * (lane & 3);
                uint2 lo = *reinterpret_cast<const uint2*>(p);
                uint2 hi = *reinterpret_cast<const uint2*>(p + 8 * TFP);
                a[mt][0] = lo.x; a[mt][2] = lo.y;
                a[mt][1] = hi.x; a[mt][3] = hi.y;
            }
            #pragma unroll
            for (int nt = 0; nt < 4; nt++) {
                int n = warp_n * 32 + nt * 8 + (lane >> 2);
                uint2 bb = *reinterpret_cast<const uint2*>(Bs + n * TFP + j * 8 + 2 * (lane & 3));
                b[nt][0] = bb.x; b[nt][1] = bb.y;
            }
            #pragma unroll
            for (int mt = 0; mt < 4; mt++)
                #pragma unroll
                for (int nt = 0; nt < 4; nt++)
                    mma_tf32(acc[mt][nt], a[mt], b[nt]);
        }
    }

    // epilogue: direct global float2 writes
    #pragma unroll
    for (int mt = 0; mt < 4; mt++) {
        #pragma unroll
        for (int rh = 0; rh < 2; rh++) {
            int r = brow + warp_m * 64 + mt * 16 + rh * 8 + (lane >> 2);
            #pragma unroll
            for (int nt = 0; nt < 4; nt++) {
                int c = bcol + warp_n * 32 + nt * 8 + 2 * (lane & 3);
                float2 v;
                v.x = acc[mt][nt][rh * 2 + 0] + bias[c];
                v.y = acc[mt][nt][rh * 2 + 1] + bias[c + 1];
                if (EPI == EPI_BIAS_RES) {
                    float2 rv = *reinterpret_cast<const float2*>(res + (size_t)r * ldc + c);
                    v.x += rv.x; v.y += rv.y;
                } else if (EPI == EPI_GELU) {
                    v.x = gelu_tanh(v.x); v.y = gelu_tanh(v.y);
                }
                *reinterpret_cast<float2*>(C + (size_t)r * ldc + c) = v;
            }
        }
    }
}

// ---------------- bf16 mma.sync score GEMM + top-16, cp.async pipelined -----
// grid(NCH, 32); CTA = 128 queries x 4096-key chunk, K=768 in 12 slices of 64.
// smem (83968 B): [0,16K) lists; buffers A0@16K B0@32K A1@48K B1@64K (16KB ea);
// Sc f32 128x132 @16K (epilogue only, overlaps buffers).
#define SC_LISTS 0
#define SC_BUF   16384
#define SC_SC    16384

__device__ __forceinline__ void stage64_async(
    uint32_t dstb, const __nv_bfloat16* __restrict__ src, int tid)
{
    #pragma unroll
    for (int it = 0; it < 4; it++) {
        int c = tid + it * 256;          // 1024 chunks = 128 rows x 8 x 16B
        int row = c >> 3, col = c & 7;
        uint32_t d = dstb + row * 128 + ((col ^ (row & 7)) << 4);
        const void* s = src + (size_t)row * DMODEL + col * 8;
        CP_ASYNC16(d, s);
    }
}

__global__ __launch_bounds__(256, 2) void score_topk_mma(
    const __nv_bfloat16* __restrict__ qb, const __nv_bfloat16* __restrict__ kb,
    float* __restrict__ part_s, int* __restrict__ part_i)
{
    extern __shared__ char dsm[];
    float (*tks)[16] = (float(*)[16])(dsm + SC_LISTS);
    int   (*tki)[16] = (int  (*)[16])(dsm + SC_LISTS + 8192);
    float (*Sc)[132] = (float(*)[132])(dsm + SC_SC);
    uint32_t sbase = smem_u32(dsm);

    int tid = threadIdx.x, lane = tid & 31, wid = tid >> 5;
    int warp_m = wid >> 2, warp_n = wid & 3;
    int q0 = blockIdx.y * 128;
    int c0 = blockIdx.x * CHUNK;

    for (int i = tid; i < 128 * 16; i += 256) {
        ((float*)tks)[i] = -CUDART_INF_F;
        ((int*)tki)[i]   = 0x7fffffff;
    }

    // ldmatrix lane row terms (relative to buffer base)
    uint32_t a_rel[4], b_rel[2];
    int a_rx[4], b_rx[2];
    #pragma unroll
    for (int mt = 0; mt < 4; mt++) {
        int row = warp_m * 64 + mt * 16 + (lane & 15);
        a_rel[mt] = row * 128;
        a_rx[mt] = row & 7;
    }
    #pragma unroll
    for (int pr = 0; pr < 2; pr++) {
        int row = warp_n * 32 + pr * 16 + (lane & 7) + ((lane >> 4) << 3);
        b_rel[pr] = row * 128;
        b_rx[pr] = row & 7;
    }
    int a_ch = lane >> 4;
    int b_ch = (lane >> 3) & 1;

    for (int kt = 0; kt < CHUNK / 128; kt++) {
        int kb0 = c0 + kt * 128;
        const __nv_bfloat16* qbase = qb + (size_t)q0  * DMODEL;
        const __nv_bfloat16* kbase = kb + (size_t)kb0 * DMODEL;

        __syncthreads();   // prev scan done: buffers may be overwritten
        stage64_async(sbase + SC_BUF,         qbase, tid);
        stage64_async(sbase + SC_BUF + 16384, kbase, tid);
        CP_COMMIT();

        float acc[4][4][4];
        #pragma unroll
        for (int mt = 0; mt < 4; mt++)
            #pragma unroll
            for (int nt = 0; nt < 4; nt++)
                #pragma unroll
                for (int r = 0; r < 4; r++) acc[mt][nt][r] = 0.f;

        for (int kc = 0; kc < DMODEL / 64; kc++) {
            int cur = kc & 1;
            CP_WAIT0();        // slice kc landed (prefetch kc+1 not yet issued)
            __syncthreads();   // visible to all; all warps past compute kc-1
            if (kc + 1 < DMODEL / 64) {   // prefetch kc+1 overlaps compute kc
                uint32_t nb = sbase + SC_BUF + ((kc + 1) & 1) * 32768;
                stage64_async(nb,         qbase + (kc + 1) * 64, tid);
                stage64_async(nb + 16384, kbase + (kc + 1) * 64, tid);
                CP_COMMIT();
            }
            uint32_t abase = sbase + SC_BUF + cur * 32768;
            uint32_t bbase = abase + 16384;

            #pragma unroll
            for (int kk = 0; kk < 4; kk++) {
                uint32_t af[4][4], bf[2][4];
                #pragma unroll
                for (int mt = 0; mt < 4; mt++) {
                    int ch = kk * 2 + a_ch;
                    ldsm_x4(af[mt][0], af[mt][1], af[mt][2], af[mt][3],
                            abase + a_rel[mt] + ((ch ^ a_rx[mt]) << 4));
                }
                #pragma unroll
                for (int pr = 0; pr < 2; pr++) {
                    int ch = kk * 2 + b_ch;
                    ldsm_x4(bf[pr][0], bf[pr][1], bf[pr][2], bf[pr][3],
                            bbase + b_rel[pr] + ((ch ^ b_rx[pr]) << 4));
                }
                #pragma unroll
                for (int mt = 0; mt < 4; mt++) {
                    mma16816(acc[mt][0], af[mt], &bf[0][0]);
                    mma16816(acc[mt][1], af[mt], &bf[0][2]);
                    mma16816(acc[mt][2], af[mt], &bf[1][0]);
                    mma16816(acc[mt][3], af[mt], &bf[1][2]);
                }
            }
        }

        // dump fragments to Sc (overlaps buffers; all cp.async drained)
        __syncthreads();
        #pragma unroll
        for (int mt = 0; mt < 4; mt++) {
            int r = warp_m * 64 + mt * 16 + (lane >> 2);
            #pragma unroll
            for (int nt = 0; nt < 4; nt++) {
                int c = warp_n * 32 + nt * 8 + 2 * (lane & 3);
                *reinterpret_cast<float2*>(&Sc[r][c])     = make_float2(acc[mt][nt][0], acc[mt][nt][1]);
                *reinterpret_cast<float2*>(&Sc[r + 8][c]) = make_float2(acc[mt][nt][2], acc[mt][nt][3]);
            }
        }
        __syncthreads();

        // top-16 scan: warp wid owns rows [wid*16, wid*16+16)
        for (int rr = 0; rr < 16; rr++) {
            int r = wid * 16 + rr;
            #pragma unroll
            for (int j = 0; j < 4; j++) {
                int c = lane + j * 32;
                float s = Sc[r][c];
                int myid = kb0 + c;
                float thr = tks[r][15];
                bool cand = (s > thr) || (s == thr && myid < tki[r][15]);
                unsigned mmask = __ballot_sync(0xffffffffu, cand);
                while (mmask) {
                    int src = __ffs(mmask) - 1; mmask &= mmask - 1;
                    if (lane == src) {
                        float th2 = tks[r][15];
                        if (s > th2 || (s == th2 && myid < tki[r][15])) {
                            int p = 15;
                            while (p > 0 && (s > tks[r][p - 1] ||
                                             (s == tks[r][p - 1] && myid < tki[r][p - 1]))) {
                                tks[r][p] = tks[r][p - 1];
                                tki[r][p] = tki[r][p - 1];
                                p--;
                            }
                            tks[r][p] = s; tki[r][p] = myid;
                        }
                    }
                    __syncwarp();
                }
            }
        }
    }

    __syncthreads();
    for (int i = tid; i < 128 * 16; i += 256) {
        int r = i >> 4, j = i & 15;
        size_t o = (((size_t)(q0 + r)) * NCH + blockIdx.x) * KSEL + j;
        part_s[o] = tks[r][j];
        part_i[o] = tki[r][j];
    }
}

// ---------------- merge 128 bf16 candidates/row -> top-32 -------------------
__global__ __launch_bounds__(256) void merge32_kernel(
    const float* __restrict__ ps, const int* __restrict__ pi, int* __restrict__ cand)
{
    int lane = threadIdx.x & 31;
    int row  = blockIdx.x * 8 + (threadIdx.x >> 5);
    float s[4]; int id[4];
    #pragma unroll
    for (int j = 0; j < 4; j++) {
        size_t e = (size_t)row * 128 + lane + 32 * j;
        s[j]  = ps[e];
        id[j] = pi[e];
    }
    for (int t = 0; t < NCAND; t++) {
        float bs = s[0]; int bid = id[0];
        #pragma unroll
        for (int j = 1; j < 4; j++)
            if (better(s[j], id[j], bs, bid)) { bs = s[j]; bid = id[j]; }
        #pragma unroll
        for (int o = 16; o > 0; o >>= 1) {
            float os = __shfl_xor_sync(0xffffffffu, bs, o);
            int   oi = __shfl_xor_sync(0xffffffffu, bid, o);
            if (better(os, oi, bs, bid)) { bs = os; bid = oi; }
        }
        if (lane == 0) cand[row * NCAND + t] = bid;
        #pragma unroll
        for (int j = 0; j < 4; j++)
            if (id[j] == bid) { s[j] = -CUDART_INF_F; id[j] = 0x7fffffff; }
    }
}

// ---------------- exact fp32 rescore of 32 candidates -> final top-16 -------
__global__ __launch_bounds__(256) void rescore_kernel(
    const float* __restrict__ q, const float* __restrict__ dbk,
    const int* __restrict__ cand, int* __restrict__ topk)
{
    __shared__ float sq[DMODEL];
    __shared__ float ss[NCAND];
    __shared__ int   sid[NCAND];
    int t = blockIdx.x, tid = threadIdx.x;
    int w = tid >> 5, lane = tid & 31;
    sq[tid]       = q[(size_t)t * DMODEL + tid];
    sq[tid + 256] = q[(size_t)t * DMODEL + tid + 256];
    sq[tid + 512] = q[(size_t)t * DMODEL + tid + 512];
    if (tid < NCAND) sid[tid] = cand[t * NCAND + tid];
    __syncthreads();

    for (int cc = w; cc < NCAND; cc += 8) {
        const float* kr = dbk + (size_t)sid[cc] * DMODEL;
        float p = 0.f;
        #pragma unroll
        for (int j = 0; j < DMODEL / 32; j++)
            p += sq[lane + 32 * j] * kr[lane + 32 * j];
        #pragma unroll
        for (int o = 16; o > 0; o >>= 1) p += __shfl_xor_sync(0xffffffffu, p, o);
        if (lane == 0) ss[cc] = p;
    }
    __syncthreads();

    if (w == 0) {
        float s = ss[lane];
        int  id = sid[lane];
        for (int it = 0; it < KSEL; it++) {
            float bs = s; int bid = id;
            #pragma unroll
            for (int o = 16; o > 0; o >>= 1) {
                float os = __shfl_xor_sync(0xffffffffu, bs, o);
                int   oi = __shfl_xor_sync(0xffffffffu, bid, o);
                if (better(os, oi, bs, bid)) { bs = os; bid = oi; }
            }
            if (lane == 0) topk[t * KSEL + it] = bid;
            if (id == bid) { s = -CUDART_INF_F; id = 0x7fffffff; }
        }
    }
}

// ---------------- per-token memory attention ---------------------------------
__global__ __launch_bounds__(384) void attn_kernel(
    const float* __restrict__ q, const float* __restrict__ dbk,
    const float* __restrict__ dbv, const int* __restrict__ topk,
    float* __restrict__ out)
{
    __shared__ float sq[DMODEL];
    __shared__ int   sidx[KSEL];
    __shared__ float saw[NH][KSEL];
    int t = blockIdx.x;
    int tid = threadIdx.x, lane = tid & 31, w = tid >> 5;
    sq[tid]       = q[(size_t)t * DMODEL + tid];
    sq[tid + 384] = q[(size_t)t * DMODEL + tid + 384];
    if (tid < KSEL) sidx[tid] = topk[t * KSEL + tid];
    __syncthreads();

    float q1 = sq[w * HD + lane], q2 = sq[w * HD + lane + 32];
    for (int m = 0; m < KSEL; m++) {
        const float* kr = dbk + (size_t)sidx[m] * DMODEL + w * HD;
        float p = q1 * kr[lane] + q2 * kr[lane + 32];
        #pragma unroll
        for (int o = 16; o > 0; o >>= 1) p += __shfl_xor_sync(0xffffffffu, p, o);
        if (lane == 0) saw[w][m] = p * 0.125f;
    }
    __syncwarp();
    {
        float x = (lane < KSEL) ? saw[w][lane] : -CUDART_INF_F;
        float mx = x;
        #pragma unroll
        for (int o = 16; o > 0; o >>= 1) mx = fmaxf(mx, __shfl_xor_sync(0xffffffffu, mx, o));
        float e = (lane < KSEL) ? expf(x - mx) : 0.f;
        float se = e;
        #pragma unroll
        for (int o = 16; o > 0; o >>= 1) se += __shfl_xor_sync(0xffffffffu, se, o);
        if (lane < KSEL) saw[w][lane] = e / se;
    }
    __syncwarp();
    float a1 = 0.f, a2 = 0.f;
    for (int m = 0; m < KSEL; m++) {
        float aw = saw[w][m];
        const float* vr = dbv + (size_t)sidx[m] * DMODEL + w * HD;
        a1 += aw * vr[lane]; a2 += aw * vr[lane + 32];
    }
    out[(size_t)t * DMODEL + w * HD + lane]      = a1;
    out[(size_t)t * DMODEL + w * HD + lane + 32] = a2;
}

// ---------------- launch -----------------------------------------------------
extern "C" void kernel_launch(void* const* d_in, const int* in_sizes, int n_in,
                              void* d_out, int out_size)
{
    const float* prev   = (const float*)d_in[0];
    const float* dbk    = (const float*)d_in[1];
    const float* dbv    = (const float*)d_in[2];
    const float* ln1g   = (const float*)d_in[3];
    const float* ln1b   = (const float*)d_in[4];
    const float* cattnw = (const float*)d_in[5];
    const float* cattnb = (const float*)d_in[6];
    const float* cprojw = (const float*)d_in[7];
    const float* cprojb = (const float*)d_in[8];
    const float* ln2g   = (const float*)d_in[9];
    const float* ln2b   = (const float*)d_in[10];
    const float* fcw    = (const float*)d_in[11];
    const float* fcb    = (const float*)d_in[12];
    const float* projw  = (const float*)d_in[13];
    const float* projb  = (const float*)d_in[14];
    float* out = (float*)d_out;

    float *p_ln, *p_q, *p_attn, *p_h, *p_ff1, *p_parts;
    __nv_bfloat16 *p_qb, *p_kb;
    int *p_parti, *p_cand, *p_topk;
    cudaGetSymbolAddress((void**)&p_ln,    g_ln);
    cudaGetSymbolAddress((void**)&p_q,     g_q);
    cudaGetSymbolAddress((void**)&p_attn,  g_attn);
    cudaGetSymbolAddress((void**)&p_h,     g_h);
    cudaGetSymbolAddress((void**)&p_ff1,   g_ff1);
    cudaGetSymbolAddress((void**)&p_qb,    g_qb);
    cudaGetSymbolAddress((void**)&p_kb,    g_kb);
    cudaGetSymbolAddress((void**)&p_parts, g_part_s);
    cudaGetSymbolAddress((void**)&p_parti, g_part_i);
    cudaGetSymbolAddress((void**)&p_cand,  g_cand);
    cudaGetSymbolAddress((void**)&p_topk,  g_topk);

    // 1. LN1
    ln_kernel<<<NTOK, 256>>>(prev, ln1g, ln1b, p_ln);

    // 2. q = LN1(x) @ c_attn_w[:, :768] + bias  (fp32 — preserves selection)
    sgemm_kernel<EPI_BIAS><<<dim3(DMODEL / 128, NTOK / 128), 256>>>(
        p_ln, DMODEL, cattnw, 3 * DMODEL, cattnb, nullptr, p_q, DMODEL, DMODEL);

    // 3. bf16 conversions for tensor-core scoring
    f2bf_kernel<<<(NTOK * DMODEL) / 1024, 256>>>(p_q, p_qb);
    f2bf_kernel<<<(MDB * DMODEL) / 1024, 256>>>(dbk, p_kb);

    // 4. bf16 mma.sync score GEMM (cp.async pipelined) + per-chunk top-16
    int smem = 16384 + 128 * 132 * 4;  // 83968 B
    cudaFuncSetAttribute(score_topk_mma,
                         cudaFuncAttributeMaxDynamicSharedMemorySize, smem);
    score_topk_mma<<<dim3(NCH, NTOK / 128), 256, smem>>>(p_qb, p_kb, p_parts, p_parti);

    // 5. merge 128 bf16 candidates -> top-32 per token
    merge32_kernel<<<NTOK / 8, 256>>>(p_parts, p_parti, p_cand);

    // 6. exact fp32 rescore of top-32 -> final top-16 (jax tie-break)
    rescore_kernel<<<NTOK, 256>>>(p_q, dbk, p_cand, p_topk);

    // 7. per-token per-head softmax attention over 16 gathered memories
    attn_kernel<<<NTOK, 384>>>(p_q, dbk, dbv, p_topk, p_attn);

    // 8. h = attn @ c_proj_w + bias + residual   (tf32 tensor cores)
    tgemm_kernel<EPI_BIAS_RES><<<dim3(DMODEL / 128, NTOK / 128), 256>>>(
        p_attn, DMODEL, cprojw, DMODEL, cprojb, prev, p_h, DMODEL, DMODEL);

    // 9. LN2
    ln_kernel<<<NTOK, 256>>>(p_h, ln2g, ln2b, p_ln);

    // 10. ff1 = gelu(LN2(h) @ fc_w + fc_b)       (tf32)
    tgemm_kernel<EPI_GELU><<<dim3(DFF / 128, NTOK / 128), 256>>>(
        p_ln, DMODEL, fcw, DFF, fcb, nullptr, p_ff1, DFF, DMODEL);

    // 11. out = ff1 @ proj_w + proj_b + h        (tf32)
    tgemm_kernel<EPI_BIAS_RES><<<dim3(DMODEL / 128, NTOK / 128), 256>>>(
        p_ff1, DFF, projw, DMODEL, projb, p_h, out, DMODEL, DFF);
}

// round 5
// speedup vs baseline: 3.0730x; 1.0081x over previous
#include <cuda_runtime.h>
#include <cuda_bf16.h>
#include <math_constants.h>
#include <cstdint>

#define NTOK   4096
#define DMODEL 768
#define NH     12
#define HD     64
#define KSEL   16
#define MDB    32768
#define NCH    8
#define CHUNK  (MDB/NCH)   /* 4096 keys per chunk */
#define DFF    3072
#define NCAND  32          /* rescored candidates per token */

// ---------------- scratch (device globals; no allocation allowed) ----------
__device__ float g_ln  [NTOK*DMODEL];
__device__ float g_q   [NTOK*DMODEL];
__device__ float g_attn[NTOK*DMODEL];
__device__ float g_h   [NTOK*DMODEL];
__device__ float g_ff1 [NTOK*DFF];
__device__ __nv_bfloat16 g_qb[NTOK*DMODEL];
__device__ __nv_bfloat16 g_kb[MDB*DMODEL];
__device__ float g_part_s[NTOK*NCH*KSEL];
__device__ int   g_part_i[NTOK*NCH*KSEL];
__device__ int   g_cand  [NTOK*NCAND];
__device__ int   g_topk  [NTOK*KSEL];

// ---------------- helpers ---------------------------------------------------
__device__ __forceinline__ uint32_t smem_u32(const void* p) {
    uint32_t a;
    asm("{ .reg .u64 t; cvta.to.shared.u64 t, %1; cvt.u32.u64 %0, t; }" : "=r"(a) : "l"(p));
    return a;
}

__device__ __forceinline__ void ldsm_x4(uint32_t& r0, uint32_t& r1,
                                        uint32_t& r2, uint32_t& r3, uint32_t addr) {
    asm volatile("ldmatrix.sync.aligned.m8n8.x4.shared.b16 {%0,%1,%2,%3}, [%4];"
                 : "=r"(r0), "=r"(r1), "=r"(r2), "=r"(r3) : "r"(addr));
}

__device__ __forceinline__ void mma16816(float* c, const uint32_t* a, const uint32_t* b) {
    asm("mma.sync.aligned.m16n8k16.row.col.f32.bf16.bf16.f32 "
        "{%0,%1,%2,%3}, {%4,%5,%6,%7}, {%8,%9}, {%0,%1,%2,%3};"
        : "+f"(c[0]), "+f"(c[1]), "+f"(c[2]), "+f"(c[3])
        : "r"(a[0]), "r"(a[1]), "r"(a[2]), "r"(a[3]), "r"(b[0]), "r"(b[1]));
}

__device__ __forceinline__ uint32_t f2tf32(float f) {
    uint32_t o; asm("cvt.rna.tf32.f32 %0, %1;" : "=r"(o) : "f"(f)); return o;
}

__device__ __forceinline__ void mma_tf32(float* c, const uint32_t* a, const uint32_t* b) {
    asm("mma.sync.aligned.m16n8k8.row.col.f32.tf32.tf32.f32 "
        "{%0,%1,%2,%3}, {%4,%5,%6,%7}, {%8,%9}, {%0,%1,%2,%3};"
        : "+f"(c[0]), "+f"(c[1]), "+f"(c[2]), "+f"(c[3])
        : "r"(a[0]), "r"(a[1]), "r"(a[2]), "r"(a[3]), "r"(b[0]), "r"(b[1]));
}

#define CP_ASYNC16(dst, src) \
    asm volatile("cp.async.cg.shared.global [%0], [%1], 16;" :: "r"(dst), "l"(src))
#define CP_ASYNC8(dst, src) \
    asm volatile("cp.async.ca.shared.global [%0], [%1], 8;" :: "r"(dst), "l"(src))
#define CP_COMMIT()  asm volatile("cp.async.commit_group;" ::: "memory")
#define CP_WAIT0()   asm volatile("cp.async.wait_group 0;" ::: "memory")

__device__ __forceinline__ float blockReduceSum(float v, float* red) {
    #pragma unroll
    for (int o = 16; o > 0; o >>= 1) v += __shfl_xor_sync(0xffffffffu, v, o);
    int w = threadIdx.x >> 5, l = threadIdx.x & 31;
    if (l == 0) red[w] = v;
    __syncthreads();
    if (w == 0) {
        float t = (l < 8) ? red[l] : 0.f;
        #pragma unroll
        for (int o = 4; o > 0; o >>= 1) t += __shfl_xor_sync(0xffffffffu, t, o);
        if (l == 0) red[0] = t;
    }
    __syncthreads();
    float r = red[0];
    __syncthreads();
    return r;
}

__device__ __forceinline__ float gelu_tanh(float x) {
    return 0.5f * x * (1.f + tanhf(0.7978845608028654f * (x + 0.044715f * x * x * x)));
}

__device__ __forceinline__ bool better(float s1, int i1, float s2, int i2) {
    return (s1 > s2) || (s1 == s2 && i1 < i2);
}

// ---------------- layernorm --------------------------------------------------
__global__ __launch_bounds__(256) void ln_kernel(
    const float* __restrict__ x, const float* __restrict__ g,
    const float* __restrict__ b, float* __restrict__ y)
{
    __shared__ float red[8];
    int row = blockIdx.x;
    const float* xr = x + (size_t)row * DMODEL;
    int t = threadIdx.x;
    float v0 = xr[t], v1 = xr[t + 256], v2 = xr[t + 512];
    float mu = blockReduceSum(v0 + v1 + v2, red) * (1.f / DMODEL);
    float d0 = v0 - mu, d1 = v1 - mu, d2 = v2 - mu;
    float var = blockReduceSum(d0 * d0 + d1 * d1 + d2 * d2, red) * (1.f / DMODEL);
    float rs = rsqrtf(var + 1e-5f);
    float* yr = y + (size_t)row * DMODEL;
    yr[t]       = d0 * rs * g[t]       + b[t];
    yr[t + 256] = d1 * rs * g[t + 256] + b[t + 256];
    yr[t + 512] = d2 * rs * g[t + 512] + b[t + 512];
}

// ---------------- combined fp32 -> bf16 convert (q then dbk) ----------------
__global__ __launch_bounds__(256) void f2bf2_kernel(
    const float* __restrict__ xq, __nv_bfloat16* __restrict__ yq,
    const float* __restrict__ xk, __nv_bfloat16* __restrict__ yk, int nq4)
{
    int i = blockIdx.x * 256 + threadIdx.x;
    const float* src; __nv_bfloat16* dst; int j;
    if (i < nq4) { src = xq; dst = yq; j = i; }
    else         { src = xk; dst = yk; j = i - nq4; }
    float4 v = reinterpret_cast<const float4*>(src)[j];
    __nv_bfloat162 a = __floats2bfloat162_rn(v.x, v.y);
    __nv_bfloat162 b = __floats2bfloat162_rn(v.z, v.w);
    reinterpret_cast<__nv_bfloat162*>(dst)[2 * j]     = a;
    reinterpret_cast<__nv_bfloat162*>(dst)[2 * j + 1] = b;
}

// ---------------- fp32 SGEMM (only used for q; preserves selection) ---------
enum { EPI_BIAS = 0, EPI_BIAS_RES = 1, EPI_GELU = 2 };

template <int EPI>
__global__ __launch_bounds__(256) void sgemm_kernel(
    const float* __restrict__ A, int lda,
    const float* __restrict__ B, int ldb,
    const float* __restrict__ bias,
    const float* __restrict__ res,
    float* __restrict__ C, int ldc, int Kd)
{
    __shared__ float As[8][128];
    __shared__ float Bs[8][128];
    int tid  = threadIdx.x;
    int brow = blockIdx.y * 128, bcol = blockIdx.x * 128;
    int arow = tid >> 1, acol = (tid & 1) * 4;
    int bkr  = tid >> 5, bcol4 = (tid & 31) * 4;
    const float* Ap = A + (size_t)(brow + arow) * lda + acol;
    const float* Bp = B + (size_t)bkr * ldb + bcol + bcol4;
    int rbase = (tid >> 4) * 4, cbase = (tid & 15) * 4;

    float acc[8][8];
    #pragma unroll
    for (int i = 0; i < 8; i++)
        #pragma unroll
        for (int j = 0; j < 8; j++) acc[i][j] = 0.f;

    for (int k0 = 0; k0 < Kd; k0 += 8) {
        float4 av = *reinterpret_cast<const float4*>(Ap + k0);
        float4 bv = *reinterpret_cast<const float4*>(Bp + (size_t)k0 * ldb);
        __syncthreads();
        As[acol + 0][arow] = av.x; As[acol + 1][arow] = av.y;
        As[acol + 2][arow] = av.z; As[acol + 3][arow] = av.w;
        *reinterpret_cast<float4*>(&Bs[bkr][bcol4]) = bv;
        __syncthreads();
        #pragma unroll
        for (int kk = 0; kk < 8; kk++) {
            float a[8], bb[8];
            *reinterpret_cast<float4*>(a)      = *reinterpret_cast<const float4*>(&As[kk][rbase]);
            *reinterpret_cast<float4*>(a + 4)  = *reinterpret_cast<const float4*>(&As[kk][rbase + 64]);
            *reinterpret_cast<float4*>(bb)     = *reinterpret_cast<const float4*>(&Bs[kk][cbase]);
            *reinterpret_cast<float4*>(bb + 4) = *reinterpret_cast<const float4*>(&Bs[kk][cbase + 64]);
            #pragma unroll
            for (int i = 0; i < 8; i++)
                #pragma unroll
                for (int j = 0; j < 8; j++) acc[i][j] += a[i] * bb[j];
        }
    }

    #pragma unroll
    for (int i = 0; i < 8; i++) {
        int r = brow + rbase + ((i < 4) ? i : 60 + i);
        #pragma unroll
        for (int jg = 0; jg < 2; jg++) {
            int c = bcol + cbase + jg * 64;
            float4 bi = *reinterpret_cast<const float4*>(bias + c);
            float4 v;
            v.x = acc[i][jg * 4 + 0] + bi.x;
            v.y = acc[i][jg * 4 + 1] + bi.y;
            v.z = acc[i][jg * 4 + 2] + bi.z;
            v.w = acc[i][jg * 4 + 3] + bi.w;
            if (EPI == EPI_BIAS_RES) {
                float4 rv = *reinterpret_cast<const float4*>(res + (size_t)r * ldc + c);
                v.x += rv.x; v.y += rv.y; v.z += rv.z; v.w += rv.w;
            } else if (EPI == EPI_GELU) {
                v.x = gelu_tanh(v.x); v.y = gelu_tanh(v.y);
                v.z = gelu_tanh(v.z); v.w = gelu_tanh(v.w);
            }
            *reinterpret_cast<float4*>(C + (size_t)r * ldc + c) = v;
        }
    }
}

// ---------------- tf32 tensor-core GEMM, cp.async double-buffered -----------
// C[M,N] = A[M,K] @ B[K,N], 128x128x16 tiles, 8 warps (2x4), 64x32 per warp.
// A smem [128][16] stride 20 (conflict-free frag reads, 8B cp.async aligned).
// B smem [16][128] stride 136 (fully coalesced 16B cp.async, conflict-free).
#define A_STR 20
#define B_STR 136
#define A_BUF (128 * A_STR)          /* floats */
#define B_BUF (16 * B_STR)

template <int EPI>
__global__ __launch_bounds__(256, 2) void tgemm_kernel(
    const float* __restrict__ A, int lda,
    const float* __restrict__ B, int ldb,
    const float* __restrict__ bias,
    const float* __restrict__ res,
    float* __restrict__ C, int ldc, int Kd)
{
    __shared__ float As[2 * A_BUF];
    __shared__ float Bs[2 * B_BUF];
    uint32_t sA = smem_u32(As), sB = smem_u32(Bs);
    int tid = threadIdx.x, lane = tid & 31, wid = tid >> 5;
    int warp_m = wid >> 2, warp_n = wid & 3;
    int brow = blockIdx.y * 128, bcol = blockIdx.x * 128;

    float acc[4][4][4];
    #pragma unroll
    for (int mt = 0; mt < 4; mt++)
        #pragma unroll
        for (int nt = 0; nt < 4; nt++)
            #pragma unroll
            for (int r = 0; r < 4; r++) acc[mt][nt][r] = 0.f;

    // staging maps
    int a_row = tid >> 1;              // pairs: 2 chunks of 8B per (row, it)
    int a_k2  = (tid & 1) * 2;         // k2 in {0,2} then +1 via it
    int b_k   = tid >> 5;              // wait, recompute below per chunk

    // stage one K-panel (16 deep) into buffer `buf`
    auto stageA = [&](int kb, int buf) {
        #pragma unroll
        for (int it = 0; it < 4; it++) {
            int c = tid + it * 256;        // 1024 chunks of 8B
            int row = c >> 3, k2 = c & 7;  // threads 0-7 -> same row, coalesced
            uint32_t d = sA + (buf * A_BUF + row * A_STR + k2 * 2) * 4;
            const void* s = A + (size_t)(brow + row) * lda + kb + k2 * 2;
            CP_ASYNC8(d, s);
        }
    };
    auto stageB = [&](int kb, int buf) {
        #pragma unroll
        for (int it = 0; it < 2; it++) {
            int c = tid + it * 256;        // 512 chunks of 16B
            int k = c >> 5, n4 = c & 31;   // fully coalesced per k-row
            uint32_t d = sB + (buf * B_BUF + k * B_STR + n4 * 4) * 4;
            const void* s = B + (size_t)(kb + k) * ldb + bcol + n4 * 4;
            CP_ASYNC16(d, s);
        }
    };

    (void)a_row; (void)a_k2; (void)b_k;
    stageA(0, 0); stageB(0, 0); CP_COMMIT();

    int niter = Kd / 16;
    for (int i = 0; i < niter; i++) {
        CP_WAIT0();
        __syncthreads();
        if (i + 1 < niter) {
            stageA((i + 1) * 16, (i + 1) & 1);
            stageB((i + 1) * 16, (i + 1) & 1);
            CP_COMMIT();
        }
        const float* Af = As + (i & 1) * A_BUF;
        const float* Bf = Bs + (i & 1) * B_BUF;

        #pragma unroll
        for (int j = 0; j < 2; j++) {
            uint32_t a[4][4], b[4][2];
            #pragma unroll
            for (int mt = 0; mt < 4; mt++) {
                int r = warp_m * 64 + mt * 16 + (lane >> 2);
                const float* pa = Af + r * A_STR + j * 8 + (lane & 3);
                a[mt][0] = f2tf32(pa[0]);
                a[mt][1] = f2tf32(pa[8 * A_STR]);
                a[mt][2] = f2tf32(pa[4]);
                a[mt][3] = f2tf32(pa[8 * A_STR + 4]);
            }
            #pragma unroll
            for (int nt = 0; nt < 4; nt++) {
                int n = warp_n * 32 + nt * 8 + (lane >> 2);
                const float* pb = Bf + (j * 8 + (lane & 3)) * B_STR + n;
                b[nt][0] = f2tf32(pb[0]);
                b[nt][1] = f2tf32(pb[4 * B_STR]);
            }
            #pragma unroll
            for (int mt = 0; mt < 4; mt++)
                #pragma unroll
                for (int nt = 0; nt < 4; nt++)
                    mma_tf32(acc[mt][nt], a[mt], b[nt]);
        }
    }

    // epilogue: direct global float2 writes
    #pragma unroll
    for (int mt = 0; mt < 4; mt++) {
        #pragma unroll
        for (int rh = 0; rh < 2; rh++) {
            int r = brow + warp_m * 64 + mt * 16 + rh * 8 + (lane >> 2);
            #pragma unroll
            for (int nt = 0; nt < 4; nt++) {
                int c = bcol + warp_n * 32 + nt * 8 + 2 * (lane & 3);
                float2 v;
                v.x = acc[mt][nt][rh * 2 + 0] + bias[c];
                v.y = acc[mt][nt][rh * 2 + 1] + bias[c + 1];
                if (EPI == EPI_BIAS_RES) {
                    float2 rv = *reinterpret_cast<const float2*>(res + (size_t)r * ldc + c);
                    v.x += rv.x; v.y += rv.y;
                } else if (EPI == EPI_GELU) {
                    v.x = gelu_tanh(v.x); v.y = gelu_tanh(v.y);
                }
                *reinterpret_cast<float2*>(C + (size_t)r * ldc + c) = v;
            }
        }
    }
}

// ---------------- bf16 mma.sync score GEMM + top-16, cp.async pipelined -----
// grid(NCH, 32); CTA = 128 queries x 4096-key chunk, K=768 in 12 slices of 64.
// smem (83968 B): [0,16K) lists; buffers A0@16K B0@32K A1@48K B1@64K (16KB ea);
// Sc f32 128x132 @16K (epilogue only, overlaps buffers).
#define SC_LISTS 0
#define SC_BUF   16384
#define SC_SC    16384

__device__ __forceinline__ void stage64_async(
    uint32_t dstb, const __nv_bfloat16* __restrict__ src, int tid)
{
    #pragma unroll
    for (int it = 0; it < 4; it++) {
        int c = tid + it * 256;          // 1024 chunks = 128 rows x 8 x 16B
        int row = c >> 3, col = c & 7;
        uint32_t d = dstb + row * 128 + ((col ^ (row & 7)) << 4);
        const void* s = src + (size_t)row * DMODEL + col * 8;
        CP_ASYNC16(d, s);
    }
}

__global__ __launch_bounds__(256, 2) void score_topk_mma(
    const __nv_bfloat16* __restrict__ qb, const __nv_bfloat16* __restrict__ kb,
    float* __restrict__ part_s, int* __restrict__ part_i)
{
    extern __shared__ char dsm[];
    float (*tks)[16] = (float(*)[16])(dsm + SC_LISTS);
    int   (*tki)[16] = (int  (*)[16])(dsm + SC_LISTS + 8192);
    float (*Sc)[132] = (float(*)[132])(dsm + SC_SC);
    uint32_t sbase = smem_u32(dsm);

    int tid = threadIdx.x, lane = tid & 31, wid = tid >> 5;
    int warp_m = wid >> 2, warp_n = wid & 3;
    int q0 = blockIdx.y * 128;
    int c0 = blockIdx.x * CHUNK;

    for (int i = tid; i < 128 * 16; i += 256) {
        ((float*)tks)[i] = -CUDART_INF_F;
        ((int*)tki)[i]   = 0x7fffffff;
    }

    // ldmatrix lane row terms (relative to buffer base)
    uint32_t a_rel[4], b_rel[2];
    int a_rx[4], b_rx[2];
    #pragma unroll
    for (int mt = 0; mt < 4; mt++) {
        int row = warp_m * 64 + mt * 16 + (lane & 15);
        a_rel[mt] = row * 128;
        a_rx[mt] = row & 7;
    }
    #pragma unroll
    for (int pr = 0; pr < 2; pr++) {
        int row = warp_n * 32 + pr * 16 + (lane & 7) + ((lane >> 4) << 3);
        b_rel[pr] = row * 128;
        b_rx[pr] = row & 7;
    }
    int a_ch = lane >> 4;
    int b_ch = (lane >> 3) & 1;

    for (int kt = 0; kt < CHUNK / 128; kt++) {
        int kb0 = c0 + kt * 128;
        const __nv_bfloat16* qbase = qb + (size_t)q0  * DMODEL;
        const __nv_bfloat16* kbase = kb + (size_t)kb0 * DMODEL;

        __syncthreads();   // prev scan done: buffers may be overwritten
        stage64_async(sbase + SC_BUF,         qbase, tid);
        stage64_async(sbase + SC_BUF + 16384, kbase, tid);
        CP_COMMIT();

        float acc[4][4][4];
        #pragma unroll
        for (int mt = 0; mt < 4; mt++)
            #pragma unroll
            for (int nt = 0; nt < 4; nt++)
                #pragma unroll
                for (int r = 0; r < 4; r++) acc[mt][nt][r] = 0.f;

        for (int kc = 0; kc < DMODEL / 64; kc++) {
            int cur = kc & 1;
            CP_WAIT0();        // slice kc landed
            __syncthreads();
            if (kc + 1 < DMODEL / 64) {   // prefetch kc+1 overlaps compute kc
                uint32_t nb = sbase + SC_BUF + ((kc + 1) & 1) * 32768;
                stage64_async(nb,         qbase + (kc + 1) * 64, tid);
                stage64_async(nb + 16384, kbase + (kc + 1) * 64, tid);
                CP_COMMIT();
            }
            uint32_t abase = sbase + SC_BUF + cur * 32768;
            uint32_t bbase = abase + 16384;

            #pragma unroll
            for (int kk = 0; kk < 4; kk++) {
                uint32_t af[4][4], bf[2][4];
                #pragma unroll
                for (int mt = 0; mt < 4; mt++) {
                    int ch = kk * 2 + a_ch;
                    ldsm_x4(af[mt][0], af[mt][1], af[mt][2], af[mt][3],
                            abase + a_rel[mt] + ((ch ^ a_rx[mt]) << 4));
                }
                #pragma unroll
                for (int pr = 0; pr < 2; pr++) {
                    int ch = kk * 2 + b_ch;
                    ldsm_x4(bf[pr][0], bf[pr][1], bf[pr][2], bf[pr][3],
                            bbase + b_rel[pr] + ((ch ^ b_rx[pr]) << 4));
                }
                #pragma unroll
                for (int mt = 0; mt < 4; mt++) {
                    mma16816(acc[mt][0], af[mt], &bf[0][0]);
                    mma16816(acc[mt][1], af[mt], &bf[0][2]);
                    mma16816(acc[mt][2], af[mt], &bf[1][0]);
                    mma16816(acc[mt][3], af[mt], &bf[1][2]);
                }
            }
        }

        // dump fragments to Sc (overlaps buffers; all cp.async drained)
        __syncthreads();
        #pragma unroll
        for (int mt = 0; mt < 4; mt++) {
            int r = warp_m * 64 + mt * 16 + (lane >> 2);
            #pragma unroll
            for (int nt = 0; nt < 4; nt++) {
                int c = warp_n * 32 + nt * 8 + 2 * (lane & 3);
                *reinterpret_cast<float2*>(&Sc[r][c])     = make_float2(acc[mt][nt][0], acc[mt][nt][1]);
                *reinterpret_cast<float2*>(&Sc[r + 8][c]) = make_float2(acc[mt][nt][2], acc[mt][nt][3]);
            }
        }
        __syncthreads();

        // top-16 scan: warp wid owns rows [wid*16, wid*16+16); float4 + 1 ballot
        for (int rr = 0; rr < 16; rr++) {
            int r = wid * 16 + rr;
            float4 v = *reinterpret_cast<const float4*>(&Sc[r][lane * 4]);
            int c0id = kb0 + lane * 4;
            float thr = tks[r][15];
            int   thi = tki[r][15];
            bool cand = better(v.x, c0id,     thr, thi) | better(v.y, c0id + 1, thr, thi)
                      | better(v.z, c0id + 2, thr, thi) | better(v.w, c0id + 3, thr, thi);
            unsigned mmask = __ballot_sync(0xffffffffu, cand);
            while (mmask) {
                int src = __ffs(mmask) - 1; mmask &= mmask - 1;
                if (lane == src) {
                    float vv[4] = {v.x, v.y, v.z, v.w};
                    #pragma unroll
                    for (int u = 0; u < 4; u++) {
                        float s = vv[u]; int myid = c0id + u;
                        if (better(s, myid, tks[r][15], tki[r][15])) {
                            int p = 15;
                            while (p > 0 && better(s, myid, tks[r][p - 1], tki[r][p - 1])) {
                                tks[r][p] = tks[r][p - 1];
                                tki[r][p] = tki[r][p - 1];
                                p--;
                            }
                            tks[r][p] = s; tki[r][p] = myid;
                        }
                    }
                }
                __syncwarp();
            }
        }
    }

    __syncthreads();
    for (int i = tid; i < 128 * 16; i += 256) {
        int r = i >> 4, j = i & 15;
        size_t o = (((size_t)(q0 + r)) * NCH + blockIdx.x) * KSEL + j;
        part_s[o] = tks[r][j];
        part_i[o] = tki[r][j];
    }
}

// ---------------- merge 128 bf16 candidates/row -> top-32 -------------------
__global__ __launch_bounds__(256) void merge32_kernel(
    const float* __restrict__ ps, const int* __restrict__ pi, int* __restrict__ cand)
{
    int lane = threadIdx.x & 31;
    int row  = blockIdx.x * 8 + (threadIdx.x >> 5);
    float s[4]; int id[4];
    #pragma unroll
    for (int j = 0; j < 4; j++) {
        size_t e = (size_t)row * 128 + lane + 32 * j;
        s[j]  = ps[e];
        id[j] = pi[e];
    }
    for (int t = 0; t < NCAND; t++) {
        float bs = s[0]; int bid = id[0];
        #pragma unroll
        for (int j = 1; j < 4; j++)
            if (better(s[j], id[j], bs, bid)) { bs = s[j]; bid = id[j]; }
        #pragma unroll
        for (int o = 16; o > 0; o >>= 1) {
            float os = __shfl_xor_sync(0xffffffffu, bs, o);
            int   oi = __shfl_xor_sync(0xffffffffu, bid, o);
            if (better(os, oi, bs, bid)) { bs = os; bid = oi; }
        }
        if (lane == 0) cand[row * NCAND + t] = bid;
        #pragma unroll
        for (int j = 0; j < 4; j++)
            if (id[j] == bid) { s[j] = -CUDART_INF_F; id[j] = 0x7fffffff; }
    }
}

// ---------------- exact fp32 rescore of 32 candidates -> final top-16 -------
__global__ __launch_bounds__(256) void rescore_kernel(
    const float* __restrict__ q, const float* __restrict__ dbk,
    const int* __restrict__ cand, int* __restrict__ topk)
{
    __shared__ float sq[DMODEL];
    __shared__ float ss[NCAND];
    __shared__ int   sid[NCAND];
    int t = blockIdx.x, tid = threadIdx.x;
    int w = tid >> 5, lane = tid & 31;
    sq[tid]       = q[(size_t)t * DMODEL + tid];
    sq[tid + 256] = q[(size_t)t * DMODEL + tid + 256];
    sq[tid + 512] = q[(size_t)t * DMODEL + tid + 512];
    if (tid < NCAND) sid[tid] = cand[t * NCAND + tid];
    __syncthreads();

    for (int cc = w; cc < NCAND; cc += 8) {
        const float* kr = dbk + (size_t)sid[cc] * DMODEL;
        float p = 0.f;
        #pragma unroll
        for (int j = 0; j < DMODEL / 32; j++)
            p += sq[lane + 32 * j] * kr[lane + 32 * j];
        #pragma unroll
        for (int o = 16; o > 0; o >>= 1) p += __shfl_xor_sync(0xffffffffu, p, o);
        if (lane == 0) ss[cc] = p;
    }
    __syncthreads();

    if (w == 0) {
        float s = ss[lane];
        int  id = sid[lane];
        for (int it = 0; it < KSEL; it++) {
            float bs = s; int bid = id;
            #pragma unroll
            for (int o = 16; o > 0; o >>= 1) {
                float os = __shfl_xor_sync(0xffffffffu, bs, o);
                int   oi = __shfl_xor_sync(0xffffffffu, bid, o);
                if (better(os, oi, bs, bid)) { bs = os; bid = oi; }
            }
            if (lane == 0) topk[t * KSEL + it] = bid;
            if (id == bid) { s = -CUDART_INF_F; id = 0x7fffffff; }
        }
    }
}

// ---------------- per-token memory attention ---------------------------------
__global__ __launch_bounds__(384) void attn_kernel(
    const float* __restrict__ q, const float* __restrict__ dbk,
    const float* __restrict__ dbv, const int* __restrict__ topk,
    float* __restrict__ out)
{
    __shared__ float sq[DMODEL];
    __shared__ int   sidx[KSEL];
    __shared__ float saw[NH][KSEL];
    int t = blockIdx.x;
    int tid = threadIdx.x, lane = tid & 31, w = tid >> 5;
    sq[tid]       = q[(size_t)t * DMODEL + tid];
    sq[tid + 384] = q[(size_t)t * DMODEL + tid + 384];
    if (tid < KSEL) sidx[tid] = topk[t * KSEL + tid];
    __syncthreads();

    float q1 = sq[w * HD + lane], q2 = sq[w * HD + lane + 32];
    for (int m = 0; m < KSEL; m++) {
        const float* kr = dbk + (size_t)sidx[m] * DMODEL + w * HD;
        float p = q1 * kr[lane] + q2 * kr[lane + 32];
        #pragma unroll
        for (int o = 16; o > 0; o >>= 1) p += __shfl_xor_sync(0xffffffffu, p, o);
        if (lane == 0) saw[w][m] = p * 0.125f;
    }
    __syncwarp();
    {
        float x = (lane < KSEL) ? saw[w][lane] : -CUDART_INF_F;
        float mx = x;
        #pragma unroll
        for (int o = 16; o > 0; o >>= 1) mx = fmaxf(mx, __shfl_xor_sync(0xffffffffu, mx, o));
        float e = (lane < KSEL) ? expf(x - mx) : 0.f;
        float se = e;
        #pragma unroll
        for (int o = 16; o > 0; o >>= 1) se += __shfl_xor_sync(0xffffffffu, se, o);
        if (lane < KSEL) saw[w][lane] = e / se;
    }
    __syncwarp();
    float a1 = 0.f, a2 = 0.f;
    for (int m = 0; m < KSEL; m++) {
        float aw = saw[w][m];
        const float* vr = dbv + (size_t)sidx[m] * DMODEL + w * HD;
        a1 += aw * vr[lane]; a2 += aw * vr[lane + 32];
    }
    out[(size_t)t * DMODEL + w * HD + lane]      = a1;
    out[(size_t)t * DMODEL + w * HD + lane + 32] = a2;
}

// ---------------- launch -----------------------------------------------------
extern "C" void kernel_launch(void* const* d_in, const int* in_sizes, int n_in,
                              void* d_out, int out_size)
{
    const float* prev   = (const float*)d_in[0];
    const float* dbk    = (const float*)d_in[1];
    const float* dbv    = (const float*)d_in[2];
    const float* ln1g   = (const float*)d_in[3];
    const float* ln1b   = (const float*)d_in[4];
    const float* cattnw = (const float*)d_in[5];
    const float* cattnb = (const float*)d_in[6];
    const float* cprojw = (const float*)d_in[7];
    const float* cprojb = (const float*)d_in[8];
    const float* ln2g   = (const float*)d_in[9];
    const float* ln2b   = (const float*)d_in[10];
    const float* fcw    = (const float*)d_in[11];
    const float* fcb    = (const float*)d_in[12];
    const float* projw  = (const float*)d_in[13];
    const float* projb  = (const float*)d_in[14];
    float* out = (float*)d_out;

    float *p_ln, *p_q, *p_attn, *p_h, *p_ff1, *p_parts;
    __nv_bfloat16 *p_qb, *p_kb;
    int *p_parti, *p_cand, *p_topk;
    cudaGetSymbolAddress((void**)&p_ln,    g_ln);
    cudaGetSymbolAddress((void**)&p_q,     g_q);
    cudaGetSymbolAddress((void**)&p_attn,  g_attn);
    cudaGetSymbolAddress((void**)&p_h,     g_h);
    cudaGetSymbolAddress((void**)&p_ff1,   g_ff1);
    cudaGetSymbolAddress((void**)&p_qb,    g_qb);
    cudaGetSymbolAddress((void**)&p_kb,    g_kb);
    cudaGetSymbolAddress((void**)&p_parts, g_part_s);
    cudaGetSymbolAddress((void**)&p_parti, g_part_i);
    cudaGetSymbolAddress((void**)&p_cand,  g_cand);
    cudaGetSymbolAddress((void**)&p_topk,  g_topk);

    // 1. LN1
    ln_kernel<<<NTOK, 256>>>(prev, ln1g, ln1b, p_ln);

    // 2. q = LN1(x) @ c_attn_w[:, :768] + bias  (fp32 — preserves selection)
    sgemm_kernel<EPI_BIAS><<<dim3(DMODEL / 128, NTOK / 128), 256>>>(
        p_ln, DMODEL, cattnw, 3 * DMODEL, cattnb, nullptr, p_q, DMODEL, DMODEL);

    // 3. bf16 conversions (single launch; makes score launch #4 for ncu)
    {
        int nq4 = NTOK * DMODEL / 4;
        int nk4 = MDB * DMODEL / 4;
        f2bf2_kernel<<<(nq4 + nk4) / 256, 256>>>(p_q, p_qb, dbk, p_kb, nq4);
    }

    // 4. bf16 mma.sync score GEMM (cp.async pipelined) + per-chunk top-16
    int smem = 16384 + 128 * 132 * 4;  // 83968 B
    cudaFuncSetAttribute(score_topk_mma,
                         cudaFuncAttributeMaxDynamicSharedMemorySize, smem);
    score_topk_mma<<<dim3(NCH, NTOK / 128), 256, smem>>>(p_qb, p_kb, p_parts, p_parti);

    // 5. merge 128 bf16 candidates -> top-32 per token
    merge32_kernel<<<NTOK / 8, 256>>>(p_parts, p_parti, p_cand);

    // 6. exact fp32 rescore of top-32 -> final top-16 (jax tie-break)
    rescore_kernel<<<NTOK, 256>>>(p_q, dbk, p_cand, p_topk);

    // 7. per-token per-head softmax attention over 16 gathered memories
    attn_kernel<<<NTOK, 384>>>(p_q, dbk, dbv, p_topk, p_attn);

    // 8. h = attn @ c_proj_w + bias + residual   (tf32 tensor cores)
    tgemm_kernel<EPI_BIAS_RES><<<dim3(DMODEL / 128, NTOK / 128), 256>>>(
        p_attn, DMODEL, cprojw, DMODEL, cprojb, prev, p_h, DMODEL, DMODEL);

    // 9. LN2
    ln_kernel<<<NTOK, 256>>>(p_h, ln2g, ln2b, p_ln);

    // 10. ff1 = gelu(LN2(h) @ fc_w + fc_b)       (tf32)
    tgemm_kernel<EPI_GELU><<<dim3(DFF / 128, NTOK / 128), 256>>>(
        p_ln, DMODEL, fcw, DFF, fcb, nullptr, p_ff1, DFF, DMODEL);

    // 11. out = ff1 @ proj_w + proj_b + h        (tf32)
    tgemm_kernel<EPI_BIAS_RES><<<dim3(DMODEL / 128, NTOK / 128), 256>>>(
        p_ff1, DFF, projw, DMODEL, projb, p_h, out, DMODEL, DFF);
}

// round 6
// speedup vs baseline: 4.2931x; 1.3971x over previous
#include <cuda_runtime.h>
#include <cuda_bf16.h>
#include <math_constants.h>
#include <cstdint>

#define NTOK   4096
#define DMODEL 768
#define NH     12
#define HD     64
#define KSEL   16
#define MDB    32768
#define NCH    8
#define CHUNK  (MDB/NCH)   /* 4096 keys per chunk */
#define DFF    3072
#define NCAND  32          /* rescored candidates per token */

// ---------------- scratch (device globals; no allocation allowed) ----------
__device__ float g_ln  [NTOK*DMODEL];
__device__ float g_q   [NTOK*DMODEL];
__device__ float g_attn[NTOK*DMODEL];
__device__ float g_h   [NTOK*DMODEL];
__device__ float g_ff1 [NTOK*DFF];
__device__ __nv_bfloat16 g_qb[NTOK*DMODEL];
__device__ __nv_bfloat16 g_kb[MDB*DMODEL];
__device__ uint32_t g_part[NTOK*NCH*KSEL];   // packed (ord16<<16 | 4095-lidx)
__device__ int   g_cand  [NTOK*NCAND];
__device__ int   g_topk  [NTOK*KSEL];

// ---------------- helpers ---------------------------------------------------
__device__ __forceinline__ uint32_t smem_u32(const void* p) {
    uint32_t a;
    asm("{ .reg .u64 t; cvta.to.shared.u64 t, %1; cvt.u32.u64 %0, t; }" : "=r"(a) : "l"(p));
    return a;
}

__device__ __forceinline__ void ldsm_x4(uint32_t& r0, uint32_t& r1,
                                        uint32_t& r2, uint32_t& r3, uint32_t addr) {
    asm volatile("ldmatrix.sync.aligned.m8n8.x4.shared.b16 {%0,%1,%2,%3}, [%4];"
                 : "=r"(r0), "=r"(r1), "=r"(r2), "=r"(r3) : "r"(addr));
}

__device__ __forceinline__ void mma16816(float* c, const uint32_t* a, const uint32_t* b) {
    asm("mma.sync.aligned.m16n8k16.row.col.f32.bf16.bf16.f32 "
        "{%0,%1,%2,%3}, {%4,%5,%6,%7}, {%8,%9}, {%0,%1,%2,%3};"
        : "+f"(c[0]), "+f"(c[1]), "+f"(c[2]), "+f"(c[3])
        : "r"(a[0]), "r"(a[1]), "r"(a[2]), "r"(a[3]), "r"(b[0]), "r"(b[1]));
}

__device__ __forceinline__ uint32_t f2tf32(float f) {
    uint32_t o; asm("cvt.rna.tf32.f32 %0, %1;" : "=r"(o) : "f"(f)); return o;
}

__device__ __forceinline__ void mma_tf32(float* c, const uint32_t* a, const uint32_t* b) {
    asm("mma.sync.aligned.m16n8k8.row.col.f32.tf32.tf32.f32 "
        "{%0,%1,%2,%3}, {%4,%5,%6,%7}, {%8,%9}, {%0,%1,%2,%3};"
        : "+f"(c[0]), "+f"(c[1]), "+f"(c[2]), "+f"(c[3])
        : "r"(a[0]), "r"(a[1]), "r"(a[2]), "r"(a[3]), "r"(b[0]), "r"(b[1]));
}

#define CP_ASYNC16(dst, src) \
    asm volatile("cp.async.cg.shared.global [%0], [%1], 16;" :: "r"(dst), "l"(src))
#define CP_ASYNC8(dst, src) \
    asm volatile("cp.async.ca.shared.global [%0], [%1], 8;" :: "r"(dst), "l"(src))
#define CP_COMMIT()  asm volatile("cp.async.commit_group;" ::: "memory")
#define CP_WAIT0()   asm volatile("cp.async.wait_group 0;" ::: "memory")

__device__ __forceinline__ float blockReduceSum(float v, float* red) {
    #pragma unroll
    for (int o = 16; o > 0; o >>= 1) v += __shfl_xor_sync(0xffffffffu, v, o);
    int w = threadIdx.x >> 5, l = threadIdx.x & 31;
    if (l == 0) red[w] = v;
    __syncthreads();
    if (w == 0) {
        float t = (l < 8) ? red[l] : 0.f;
        #pragma unroll
        for (int o = 4; o > 0; o >>= 1) t += __shfl_xor_sync(0xffffffffu, t, o);
        if (l == 0) red[0] = t;
    }
    __syncthreads();
    float r = red[0];
    __syncthreads();
    return r;
}

__device__ __forceinline__ float gelu_tanh(float x) {
    return 0.5f * x * (1.f + tanhf(0.7978845608028654f * (x + 0.044715f * x * x * x)));
}

__device__ __forceinline__ bool better(float s1, int i1, float s2, int i2) {
    return (s1 > s2) || (s1 == s2 && i1 < i2);
}

// pack score (bf16-order-preserving) + local idx into one sortable uint32
__device__ __forceinline__ uint32_t packkey(float s, int colLocal) {
    uint16_t b = __bfloat16_as_ushort(__float2bfloat16(s));
    uint16_t o = (b & 0x8000) ? (uint16_t)(~b) : (uint16_t)(b | 0x8000);
    return ((uint32_t)o << 16) | (uint32_t)(4095 - colLocal);
}

// warp-wide insert of key k into sorted-desc list (entry `lane`, lanes 0..15)
__device__ __forceinline__ void ins16(uint32_t& val, uint32_t k, int lane) {
    unsigned gt = __ballot_sync(0xffffffffu, k > val);
    uint32_t up = __shfl_up_sync(0xffffffffu, val, 1);
    if (gt) {
        int p = __ffs(gt) - 1;
        if (lane > p && lane < 16) val = up;
        if (lane == p) val = k;
    }
}

// ---------------- layernorm --------------------------------------------------
__global__ __launch_bounds__(256) void ln_kernel(
    const float* __restrict__ x, const float* __restrict__ g,
    const float* __restrict__ b, float* __restrict__ y)
{
    __shared__ float red[8];
    int row = blockIdx.x;
    const float* xr = x + (size_t)row * DMODEL;
    int t = threadIdx.x;
    float v0 = xr[t], v1 = xr[t + 256], v2 = xr[t + 512];
    float mu = blockReduceSum(v0 + v1 + v2, red) * (1.f / DMODEL);
    float d0 = v0 - mu, d1 = v1 - mu, d2 = v2 - mu;
    float var = blockReduceSum(d0 * d0 + d1 * d1 + d2 * d2, red) * (1.f / DMODEL);
    float rs = rsqrtf(var + 1e-5f);
    float* yr = y + (size_t)row * DMODEL;
    yr[t]       = d0 * rs * g[t]       + b[t];
    yr[t + 256] = d1 * rs * g[t + 256] + b[t + 256];
    yr[t + 512] = d2 * rs * g[t + 512] + b[t + 512];
}

// ---------------- combined fp32 -> bf16 convert (q then dbk) ----------------
__global__ __launch_bounds__(256) void f2bf2_kernel(
    const float* __restrict__ xq, __nv_bfloat16* __restrict__ yq,
    const float* __restrict__ xk, __nv_bfloat16* __restrict__ yk, int nq4)
{
    int i = blockIdx.x * 256 + threadIdx.x;
    const float* src; __nv_bfloat16* dst; int j;
    if (i < nq4) { src = xq; dst = yq; j = i; }
    else         { src = xk; dst = yk; j = i - nq4; }
    float4 v = reinterpret_cast<const float4*>(src)[j];
    __nv_bfloat162 a = __floats2bfloat162_rn(v.x, v.y);
    __nv_bfloat162 b = __floats2bfloat162_rn(v.z, v.w);
    reinterpret_cast<__nv_bfloat162*>(dst)[2 * j]     = a;
    reinterpret_cast<__nv_bfloat162*>(dst)[2 * j + 1] = b;
}

// ---------------- fp32 SGEMM (only used for q; preserves selection) ---------
enum { EPI_BIAS = 0, EPI_BIAS_RES = 1, EPI_GELU = 2 };

template <int EPI>
__global__ __launch_bounds__(256) void sgemm_kernel(
    const float* __restrict__ A, int lda,
    const float* __restrict__ B, int ldb,
    const float* __restrict__ bias,
    const float* __restrict__ res,
    float* __restrict__ C, int ldc, int Kd)
{
    __shared__ float As[8][128];
    __shared__ float Bs[8][128];
    int tid  = threadIdx.x;
    int brow = blockIdx.y * 128, bcol = blockIdx.x * 128;
    int arow = tid >> 1, acol = (tid & 1) * 4;
    int bkr  = tid >> 5, bcol4 = (tid & 31) * 4;
    const float* Ap = A + (size_t)(brow + arow) * lda + acol;
    const float* Bp = B + (size_t)bkr * ldb + bcol + bcol4;
    int rbase = (tid >> 4) * 4, cbase = (tid & 15) * 4;

    float acc[8][8];
    #pragma unroll
    for (int i = 0; i < 8; i++)
        #pragma unroll
        for (int j = 0; j < 8; j++) acc[i][j] = 0.f;

    for (int k0 = 0; k0 < Kd; k0 += 8) {
        float4 av = *reinterpret_cast<const float4*>(Ap + k0);
        float4 bv = *reinterpret_cast<const float4*>(Bp + (size_t)k0 * ldb);
        __syncthreads();
        As[acol + 0][arow] = av.x; As[acol + 1][arow] = av.y;
        As[acol + 2][arow] = av.z; As[acol + 3][arow] = av.w;
        *reinterpret_cast<float4*>(&Bs[bkr][bcol4]) = bv;
        __syncthreads();
        #pragma unroll
        for (int kk = 0; kk < 8; kk++) {
            float a[8], bb[8];
            *reinterpret_cast<float4*>(a)      = *reinterpret_cast<const float4*>(&As[kk][rbase]);
            *reinterpret_cast<float4*>(a + 4)  = *reinterpret_cast<const float4*>(&As[kk][rbase + 64]);
            *reinterpret_cast<float4*>(bb)     = *reinterpret_cast<const float4*>(&Bs[kk][cbase]);
            *reinterpret_cast<float4*>(bb + 4) = *reinterpret_cast<const float4*>(&Bs[kk][cbase + 64]);
            #pragma unroll
            for (int i = 0; i < 8; i++)
                #pragma unroll
                for (int j = 0; j < 8; j++) acc[i][j] += a[i] * bb[j];
        }
    }

    #pragma unroll
    for (int i = 0; i < 8; i++) {
        int r = brow + rbase + ((i < 4) ? i : 60 + i);
        #pragma unroll
        for (int jg = 0; jg < 2; jg++) {
            int c = bcol + cbase + jg * 64;
            float4 bi = *reinterpret_cast<const float4*>(bias + c);
            float4 v;
            v.x = acc[i][jg * 4 + 0] + bi.x;
            v.y = acc[i][jg * 4 + 1] + bi.y;
            v.z = acc[i][jg * 4 + 2] + bi.z;
            v.w = acc[i][jg * 4 + 3] + bi.w;
            if (EPI == EPI_BIAS_RES) {
                float4 rv = *reinterpret_cast<const float4*>(res + (size_t)r * ldc + c);
                v.x += rv.x; v.y += rv.y; v.z += rv.z; v.w += rv.w;
            } else if (EPI == EPI_GELU) {
                v.x = gelu_tanh(v.x); v.y = gelu_tanh(v.y);
                v.z = gelu_tanh(v.z); v.w = gelu_tanh(v.w);
            }
            *reinterpret_cast<float4*>(C + (size_t)r * ldc + c) = v;
        }
    }
}

// ---------------- tf32 tensor-core GEMM, cp.async double-buffered -----------
#define A_STR 20
#define B_STR 136
#define A_BUF (128 * A_STR)
#define B_BUF (16 * B_STR)

template <int EPI>
__global__ __launch_bounds__(256, 2) void tgemm_kernel(
    const float* __restrict__ A, int lda,
    const float* __restrict__ B, int ldb,
    const float* __restrict__ bias,
    const float* __restrict__ res,
    float* __restrict__ C, int ldc, int Kd)
{
    __shared__ float As[2 * A_BUF];
    __shared__ float Bs[2 * B_BUF];
    uint32_t sA = smem_u32(As), sB = smem_u32(Bs);
    int tid = threadIdx.x, lane = tid & 31, wid = tid >> 5;
    int warp_m = wid >> 2, warp_n = wid & 3;
    int brow = blockIdx.y * 128, bcol = blockIdx.x * 128;

    float acc[4][4][4];
    #pragma unroll
    for (int mt = 0; mt < 4; mt++)
        #pragma unroll
        for (int nt = 0; nt < 4; nt++)
            #pragma unroll
            for (int r = 0; r < 4; r++) acc[mt][nt][r] = 0.f;

    auto stageA = [&](int kb, int buf) {
        #pragma unroll
        for (int it = 0; it < 4; it++) {
            int c = tid + it * 256;
            int row = c >> 3, k2 = c & 7;
            uint32_t d = sA + (buf * A_BUF + row * A_STR + k2 * 2) * 4;
            const void* s = A + (size_t)(brow + row) * lda + kb + k2 * 2;
            CP_ASYNC8(d, s);
        }
    };
    auto stageB = [&](int kb, int buf) {
        #pragma unroll
        for (int it = 0; it < 2; it++) {
            int c = tid + it * 256;
            int k = c >> 5, n4 = c & 31;
            uint32_t d = sB + (buf * B_BUF + k * B_STR + n4 * 4) * 4;
            const void* s = B + (size_t)(kb + k) * ldb + bcol + n4 * 4;
            CP_ASYNC16(d, s);
        }
    };

    stageA(0, 0); stageB(0, 0); CP_COMMIT();

    int niter = Kd / 16;
    for (int i = 0; i < niter; i++) {
        CP_WAIT0();
        __syncthreads();
        if (i + 1 < niter) {
            stageA((i + 1) * 16, (i + 1) & 1);
            stageB((i + 1) * 16, (i + 1) & 1);
            CP_COMMIT();
        }
        const float* Af = As + (i & 1) * A_BUF;
        const float* Bf = Bs + (i & 1) * B_BUF;

        #pragma unroll
        for (int j = 0; j < 2; j++) {
            uint32_t a[4][4], b[4][2];
            #pragma unroll
            for (int mt = 0; mt < 4; mt++) {
                int r = warp_m * 64 + mt * 16 + (lane >> 2);
                const float* pa = Af + r * A_STR + j * 8 + (lane & 3);
                a[mt][0] = f2tf32(pa[0]);
                a[mt][1] = f2tf32(pa[8 * A_STR]);
                a[mt][2] = f2tf32(pa[4]);
                a[mt][3] = f2tf32(pa[8 * A_STR + 4]);
            }
            #pragma unroll
            for (int nt = 0; nt < 4; nt++) {
                int n = warp_n * 32 + nt * 8 + (lane >> 2);
                const float* pb = Bf + (j * 8 + (lane & 3)) * B_STR + n;
                b[nt][0] = f2tf32(pb[0]);
                b[nt][1] = f2tf32(pb[4 * B_STR]);
            }
            #pragma unroll
            for (int mt = 0; mt < 4; mt++)
                #pragma unroll
                for (int nt = 0; nt < 4; nt++)
                    mma_tf32(acc[mt][nt], a[mt], b[nt]);
        }
    }

    #pragma unroll
    for (int mt = 0; mt < 4; mt++) {
        #pragma unroll
        for (int rh = 0; rh < 2; rh++) {
            int r = brow + warp_m * 64 + mt * 16 + rh * 8 + (lane >> 2);
            #pragma unroll
            for (int nt = 0; nt < 4; nt++) {
                int c = bcol + warp_n * 32 + nt * 8 + 2 * (lane & 3);
                float2 v;
                v.x = acc[mt][nt][rh * 2 + 0] + bias[c];
                v.y = acc[mt][nt][rh * 2 + 1] + bias[c + 1];
                if (EPI == EPI_BIAS_RES) {
                    float2 rv = *reinterpret_cast<const float2*>(res + (size_t)r * ldc + c);
                    v.x += rv.x; v.y += rv.y;
                } else if (EPI == EPI_GELU) {
                    v.x = gelu_tanh(v.x); v.y = gelu_tanh(v.y);
                }
                *reinterpret_cast<float2*>(C + (size_t)r * ldc + c) = v;
            }
        }
    }
}

// ---------------- bf16 mma.sync score GEMM + register top-16 ----------------
// grid(NCH, 32); CTA = 128 q x 4096-key chunk, K=768 in 12 slices of 64.
// smem 100352 B: buf0 A@0 B@16K; buf1 A@32K B@48K; Sc uint32[128][132] @32K
// (Sc overlaps buf1 only; buf0 disjoint -> next-kt slice0 stages during scan).
#define SC_SC 32768

__device__ __forceinline__ void stage64_async(
    uint32_t dstb, const __nv_bfloat16* __restrict__ src, int tid)
{
    #pragma unroll
    for (int it = 0; it < 4; it++) {
        int c = tid + it * 256;          // 1024 chunks = 128 rows x 8 x 16B
        int row = c >> 3, col = c & 7;
        uint32_t d = dstb + row * 128 + ((col ^ (row & 7)) << 4);
        const void* s = src + (size_t)row * DMODEL + col * 8;
        CP_ASYNC16(d, s);
    }
}

__global__ __launch_bounds__(256, 2) void score_topk_mma(
    const __nv_bfloat16* __restrict__ qb, const __nv_bfloat16* __restrict__ kb,
    uint32_t* __restrict__ part)
{
    extern __shared__ char dsm[];
    uint32_t (*Sc)[132] = (uint32_t(*)[132])(dsm + SC_SC);
    uint32_t sbase = smem_u32(dsm);

    int tid = threadIdx.x, lane = tid & 31, wid = tid >> 5;
    int warp_m = wid >> 2, warp_n = wid & 3;
    int q0 = blockIdx.y * 128;
    int c0 = blockIdx.x * CHUNK;

    // register top-16 lists: lst[r] = entry `lane` of row (wid*16+r), sorted desc
    uint32_t lst[16];
    #pragma unroll
    for (int r = 0; r < 16; r++) lst[r] = (lane < 16) ? 0u : 0xffffffffu;

    uint32_t a_rel[4], b_rel[2];
    int a_rx[4], b_rx[2];
    #pragma unroll
    for (int mt = 0; mt < 4; mt++) {
        int row = warp_m * 64 + mt * 16 + (lane & 15);
        a_rel[mt] = row * 128;
        a_rx[mt] = row & 7;
    }
    #pragma unroll
    for (int pr = 0; pr < 2; pr++) {
        int row = warp_n * 32 + pr * 16 + (lane & 7) + ((lane >> 4) << 3);
        b_rel[pr] = row * 128;
        b_rx[pr] = row & 7;
    }
    int a_ch = lane >> 4;
    int b_ch = (lane >> 3) & 1;

    const __nv_bfloat16* qbase = qb + (size_t)q0 * DMODEL;

    // prologue: stage kt=0 slice 0 into buf0
    stage64_async(sbase,         qbase, tid);
    stage64_async(sbase + 16384, kb + (size_t)c0 * DMODEL, tid);
    CP_COMMIT();

    for (int kt = 0; kt < CHUNK / 128; kt++) {
        int kb0 = c0 + kt * 128;
        const __nv_bfloat16* kbase = kb + (size_t)kb0 * DMODEL;

        float acc[4][4][4];
        #pragma unroll
        for (int mt = 0; mt < 4; mt++)
            #pragma unroll
            for (int nt = 0; nt < 4; nt++)
                #pragma unroll
                for (int r = 0; r < 4; r++) acc[mt][nt][r] = 0.f;

        for (int kc = 0; kc < DMODEL / 64; kc++) {
            CP_WAIT0();
            __syncthreads();
            if (kc + 1 < DMODEL / 64) {   // prefetch next slice of this kt
                uint32_t nb = sbase + ((kc + 1) & 1) * 32768;
                stage64_async(nb,         qbase + (kc + 1) * 64, tid);
                stage64_async(nb + 16384, kbase + (kc + 1) * 64, tid);
                CP_COMMIT();
            }
            uint32_t abase = sbase + (kc & 1) * 32768;
            uint32_t bbase = abase + 16384;

            #pragma unroll
            for (int kk = 0; kk < 4; kk++) {
                uint32_t af[4][4], bf[2][4];
                #pragma unroll
                for (int mt = 0; mt < 4; mt++) {
                    int ch = kk * 2 + a_ch;
                    ldsm_x4(af[mt][0], af[mt][1], af[mt][2], af[mt][3],
                            abase + a_rel[mt] + ((ch ^ a_rx[mt]) << 4));
                }
                #pragma unroll
                for (int pr = 0; pr < 2; pr++) {
                    int ch = kk * 2 + b_ch;
                    ldsm_x4(bf[pr][0], bf[pr][1], bf[pr][2], bf[pr][3],
                            bbase + b_rel[pr] + ((ch ^ b_rx[pr]) << 4));
                }
                #pragma unroll
                for (int mt = 0; mt < 4; mt++) {
                    mma16816(acc[mt][0], af[mt], &bf[0][0]);
                    mma16816(acc[mt][1], af[mt], &bf[0][2]);
                    mma16816(acc[mt][2], af[mt], &bf[1][0]);
                    mma16816(acc[mt][3], af[mt], &bf[1][2]);
                }
            }
        }

        // dump packed keys to Sc (clobbers buf1 region; mainloop done)
        __syncthreads();
        #pragma unroll
        for (int mt = 0; mt < 4; mt++) {
            int r = warp_m * 64 + mt * 16 + (lane >> 2);
            #pragma unroll
            for (int nt = 0; nt < 4; nt++) {
                int c = warp_n * 32 + nt * 8 + 2 * (lane & 3);
                int cl = kt * 128 + c;
                uint2 k0 = make_uint2(packkey(acc[mt][nt][0], cl),
                                      packkey(acc[mt][nt][1], cl + 1));
                uint2 k1 = make_uint2(packkey(acc[mt][nt][2], cl),
                                      packkey(acc[mt][nt][3], cl + 1));
                *reinterpret_cast<uint2*>(&Sc[r][c])     = k0;
                *reinterpret_cast<uint2*>(&Sc[r + 8][c]) = k1;
            }
        }
        __syncthreads();

        // stage next kt's slice0 into buf0 (disjoint from Sc) — overlaps scan
        if (kt + 1 < CHUNK / 128) {
            stage64_async(sbase,         qbase, tid);
            stage64_async(sbase + 16384, kb + (size_t)(kb0 + 128) * DMODEL, tid);
            CP_COMMIT();
        }

        // scan: warp wid owns rows [wid*16, wid*16+16); register lists
        #pragma unroll
        for (int r = 0; r < 16; r++) {
            int row = wid * 16 + r;
            uint4 kv = *reinterpret_cast<const uint4*>(&Sc[row][lane * 4]);
            uint32_t thr = __shfl_sync(0xffffffffu, lst[r], 15);
            bool c = (kv.x > thr) | (kv.y > thr) | (kv.z > thr) | (kv.w > thr);
            unsigned m = __ballot_sync(0xffffffffu, c);
            while (m) {
                int src = __ffs(m) - 1; m &= m - 1;
                uint32_t k0 = __shfl_sync(0xffffffffu, kv.x, src);
                uint32_t k1 = __shfl_sync(0xffffffffu, kv.y, src);
                uint32_t k2 = __shfl_sync(0xffffffffu, kv.z, src);
                uint32_t k3 = __shfl_sync(0xffffffffu, kv.w, src);
                thr = __shfl_sync(0xffffffffu, lst[r], 15);
                if (k0 > thr) { ins16(lst[r], k0, lane); thr = __shfl_sync(0xffffffffu, lst[r], 15); }
                if (k1 > thr) { ins16(lst[r], k1, lane); thr = __shfl_sync(0xffffffffu, lst[r], 15); }
                if (k2 > thr) { ins16(lst[r], k2, lane); thr = __shfl_sync(0xffffffffu, lst[r], 15); }
                if (k3 > thr) { ins16(lst[r], k3, lane); }
            }
        }
        __syncthreads();   // scan done before next mainloop clobbers Sc (buf1)
    }

    // write per-(row, chunk) 16-lists
    if (lane < 16) {
        #pragma unroll
        for (int r = 0; r < 16; r++) {
            int row = q0 + wid * 16 + r;
            part[((size_t)row * NCH + blockIdx.x) * KSEL + lane] = lst[r];
        }
    }
}

// ---------------- merge 128 packed candidates/row -> top-32 -----------------
__global__ __launch_bounds__(256) void merge32_kernel(
    const uint32_t* __restrict__ part, int* __restrict__ cand)
{
    int lane = threadIdx.x & 31;
    int row  = blockIdx.x * 8 + (threadIdx.x >> 5);
    unsigned long long mk[4];
    #pragma unroll
    for (int j = 0; j < 4; j++) {
        int e = lane + 32 * j;                // 0..127 = chunk*16 + slot
        uint32_t key = part[(size_t)row * 128 + e];
        int gid = (e >> 4) * CHUNK + 4095 - (int)(key & 0xfffu);
        mk[j] = ((unsigned long long)(key >> 16) << 32) | (uint32_t)(0xffffffffu - gid);
    }
    for (int t = 0; t < NCAND; t++) {
        unsigned long long best = mk[0];
        #pragma unroll
        for (int j = 1; j < 4; j++) if (mk[j] > best) best = mk[j];
        #pragma unroll
        for (int o = 16; o > 0; o >>= 1) {
            unsigned long long ob = __shfl_xor_sync(0xffffffffu, best, o);
            if (ob > best) best = ob;
        }
        if (lane == 0)
            cand[row * NCAND + t] = (int)(0xffffffffu - (uint32_t)best);
        #pragma unroll
        for (int j = 0; j < 4; j++) if (mk[j] == best) mk[j] = 0;
    }
}

// ---------------- exact fp32 rescore of 32 candidates -> final top-16 -------
__global__ __launch_bounds__(256) void rescore_kernel(
    const float* __restrict__ q, const float* __restrict__ dbk,
    const int* __restrict__ cand, int* __restrict__ topk)
{
    __shared__ float sq[DMODEL];
    __shared__ float ss[NCAND];
    __shared__ int   sid[NCAND];
    int t = blockIdx.x, tid = threadIdx.x;
    int w = tid >> 5, lane = tid & 31;
    sq[tid]       = q[(size_t)t * DMODEL + tid];
    sq[tid + 256] = q[(size_t)t * DMODEL + tid + 256];
    sq[tid + 512] = q[(size_t)t * DMODEL + tid + 512];
    if (tid < NCAND) sid[tid] = cand[t * NCAND + tid];
    __syncthreads();

    for (int cc = w; cc < NCAND; cc += 8) {
        const float* kr = dbk + (size_t)sid[cc] * DMODEL;
        float p = 0.f;
        #pragma unroll
        for (int j = 0; j < DMODEL / 32; j++)
            p += sq[lane + 32 * j] * kr[lane + 32 * j];
        #pragma unroll
        for (int o = 16; o > 0; o >>= 1) p += __shfl_xor_sync(0xffffffffu, p, o);
        if (lane == 0) ss[cc] = p;
    }
    __syncthreads();

    if (w == 0) {
        float s = ss[lane];
        int  id = sid[lane];
        for (int it = 0; it < KSEL; it++) {
            float bs = s; int bid = id;
            #pragma unroll
            for (int o = 16; o > 0; o >>= 1) {
                float os = __shfl_xor_sync(0xffffffffu, bs, o);
                int   oi = __shfl_xor_sync(0xffffffffu, bid, o);
                if (better(os, oi, bs, bid)) { bs = os; bid = oi; }
            }
            if (lane == 0) topk[t * KSEL + it] = bid;
            if (id == bid) { s = -CUDART_INF_F; id = 0x7fffffff; }
        }
    }
}

// ---------------- per-token memory attention ---------------------------------
__global__ __launch_bounds__(384) void attn_kernel(
    const float* __restrict__ q, const float* __restrict__ dbk,
    const float* __restrict__ dbv, const int* __restrict__ topk,
    float* __restrict__ out)
{
    __shared__ float sq[DMODEL];
    __shared__ int   sidx[KSEL];
    __shared__ float saw[NH][KSEL];
    int t = blockIdx.x;
    int tid = threadIdx.x, lane = tid & 31, w = tid >> 5;
    sq[tid]       = q[(size_t)t * DMODEL + tid];
    sq[tid + 384] = q[(size_t)t * DMODEL + tid + 384];
    if (tid < KSEL) sidx[tid] = topk[t * KSEL + tid];
    __syncthreads();

    float q1 = sq[w * HD + lane], q2 = sq[w * HD + lane + 32];
    for (int m = 0; m < KSEL; m++) {
        const float* kr = dbk + (size_t)sidx[m] * DMODEL + w * HD;
        float p = q1 * kr[lane] + q2 * kr[lane + 32];
        #pragma unroll
        for (int o = 16; o > 0; o >>= 1) p += __shfl_xor_sync(0xffffffffu, p, o);
        if (lane == 0) saw[w][m] = p * 0.125f;
    }
    __syncwarp();
    {
        float x = (lane < KSEL) ? saw[w][lane] : -CUDART_INF_F;
        float mx = x;
        #pragma unroll
        for (int o = 16; o > 0; o >>= 1) mx = fmaxf(mx, __shfl_xor_sync(0xffffffffu, mx, o));
        float e = (lane < KSEL) ? expf(x - mx) : 0.f;
        float se = e;
        #pragma unroll
        for (int o = 16; o > 0; o >>= 1) se += __shfl_xor_sync(0xffffffffu, se, o);
        if (lane < KSEL) saw[w][lane] = e / se;
    }
    __syncwarp();
    float a1 = 0.f, a2 = 0.f;
    for (int m = 0; m < KSEL; m++) {
        float aw = saw[w][m];
        const float* vr = dbv + (size_t)sidx[m] * DMODEL + w * HD;
        a1 += aw * vr[lane]; a2 += aw * vr[lane + 32];
    }
    out[(size_t)t * DMODEL + w * HD + lane]      = a1;
    out[(size_t)t * DMODEL + w * HD + lane + 32] = a2;
}

// ---------------- launch -----------------------------------------------------
extern "C" void kernel_launch(void* const* d_in, const int* in_sizes, int n_in,
                              void* d_out, int out_size)
{
    const float* prev   = (const float*)d_in[0];
    const float* dbk    = (const float*)d_in[1];
    const float* dbv    = (const float*)d_in[2];
    const float* ln1g   = (const float*)d_in[3];
    const float* ln1b   = (const float*)d_in[4];
    const float* cattnw = (const float*)d_in[5];
    const float* cattnb = (const float*)d_in[6];
    const float* cprojw = (const float*)d_in[7];
    const float* cprojb = (const float*)d_in[8];
    const float* ln2g   = (const float*)d_in[9];
    const float* ln2b   = (const float*)d_in[10];
    const float* fcw    = (const float*)d_in[11];
    const float* fcb    = (const float*)d_in[12];
    const float* projw  = (const float*)d_in[13];
    const float* projb  = (const float*)d_in[14];
    float* out = (float*)d_out;

    float *p_ln, *p_q, *p_attn, *p_h, *p_ff1;
    __nv_bfloat16 *p_qb, *p_kb;
    uint32_t *p_part;
    int *p_cand, *p_topk;
    cudaGetSymbolAddress((void**)&p_ln,    g_ln);
    cudaGetSymbolAddress((void**)&p_q,     g_q);
    cudaGetSymbolAddress((void**)&p_attn,  g_attn);
    cudaGetSymbolAddress((void**)&p_h,     g_h);
    cudaGetSymbolAddress((void**)&p_ff1,   g_ff1);
    cudaGetSymbolAddress((void**)&p_qb,    g_qb);
    cudaGetSymbolAddress((void**)&p_kb,    g_kb);
    cudaGetSymbolAddress((void**)&p_part,  g_part);
    cudaGetSymbolAddress((void**)&p_cand,  g_cand);
    cudaGetSymbolAddress((void**)&p_topk,  g_topk);

    // 1. LN1
    ln_kernel<<<NTOK, 256>>>(prev, ln1g, ln1b, p_ln);

    // 2. q = LN1(x) @ c_attn_w[:, :768] + bias  (fp32 — preserves selection)
    sgemm_kernel<EPI_BIAS><<<dim3(DMODEL / 128, NTOK / 128), 256>>>(
        p_ln, DMODEL, cattnw, 3 * DMODEL, cattnb, nullptr, p_q, DMODEL, DMODEL);

    // 3. bf16 conversions (single launch)
    {
        int nq4 = NTOK * DMODEL / 4;
        int nk4 = MDB * DMODEL / 4;
        f2bf2_kernel<<<(nq4 + nk4) / 256, 256>>>(p_q, p_qb, dbk, p_kb, nq4);
    }

    // 4. bf16 mma.sync score GEMM + register top-16 (packed keys)
    int smem = 32768 + 128 * 132 * 4;  // 100352 B
    cudaFuncSetAttribute(score_topk_mma,
                         cudaFuncAttributeMaxDynamicSharedMemorySize, smem);
    score_topk_mma<<<dim3(NCH, NTOK / 128), 256, smem>>>(p_qb, p_kb, p_part);

    // 5. merge 128 packed candidates -> top-32 per token
    merge32_kernel<<<NTOK / 8, 256>>>(p_part, p_cand);

    // 6. exact fp32 rescore of top-32 -> final top-16 (jax tie-break)
    rescore_kernel<<<NTOK, 256>>>(p_q, dbk, p_cand, p_topk);

    // 7. per-token per-head softmax attention over 16 gathered memories
    attn_kernel<<<NTOK, 384>>>(p_q, dbk, dbv, p_topk, p_attn);

    // 8. h = attn @ c_proj_w + bias + residual   (tf32 tensor cores)
    tgemm_kernel<EPI_BIAS_RES><<<dim3(DMODEL / 128, NTOK / 128), 256>>>(
        p_attn, DMODEL, cprojw, DMODEL, cprojb, prev, p_h, DMODEL, DMODEL);

    // 9. LN2
    ln_kernel<<<NTOK, 256>>>(p_h, ln2g, ln2b, p_ln);

    // 10. ff1 = gelu(LN2(h) @ fc_w + fc_b)       (tf32)
    tgemm_kernel<EPI_GELU><<<dim3(DFF / 128, NTOK / 128), 256>>>(
        p_ln, DMODEL, fcw, DFF, fcb, nullptr, p_ff1, DFF, DMODEL);

    // 11. out = ff1 @ proj_w + proj_b + h        (tf32)
    tgemm_kernel<EPI_BIAS_RES><<<dim3(DMODEL / 128, NTOK / 128), 256>>>(
        p_ff1, DFF, projw, DMODEL, projb, p_h, out, DMODEL, DFF);
}